// round 1
// baseline (speedup 1.0000x reference)
#include <cuda_runtime.h>
#include <math.h>

#define BSZ 2
#define LEN 4096
#define TT (BSZ*LEN)          // 8192 tokens
#define DM 768
#define DI 1536
#define DS 16
#define NH 24
#define HD 64
#define CD 1568               // DI + 2*DS
#define DP 3128               // 2*DI + 2*DS + NH
#define NC 64                 // chunks
#define CH 64                 // chunk length (LEN/NC)

// ---------------- scratch (static device arrays; no runtime alloc) ----------
__device__ float g_u[TT*DM];
__device__ float g_zx[(size_t)TT*DP];
__device__ float g_xbc[(size_t)TT*CD];
__device__ float g_dt[TT*NH];
__device__ float g_dA[TT*NH];
__device__ float g_y[(size_t)TT*DI];
__device__ float g_g[(size_t)TT*DI];
__device__ float g_hl[BSZ*NH*NC*HD*DS];
__device__ float g_hs[BSZ*NH*NC*HD*DS];
__device__ float g_P[BSZ*NH*NC];

// ---------------- layernorm: one block per token row ------------------------
__global__ void k_ln(const float* __restrict__ x, const float* __restrict__ w,
                     const float* __restrict__ bb) {
    int row = blockIdx.x;
    int tid = threadIdx.x;
    const float* xr = x + (size_t)row * DM;
    float v0 = xr[tid], v1 = xr[tid + 256], v2 = xr[tid + 512];
    float s  = v0 + v1 + v2;
    float sq = v0*v0 + v1*v1 + v2*v2;
    __shared__ float sh[16];
    #pragma unroll
    for (int m = 16; m; m >>= 1) {
        s  += __shfl_xor_sync(0xffffffffu, s,  m);
        sq += __shfl_xor_sync(0xffffffffu, sq, m);
    }
    if ((tid & 31) == 0) { sh[tid >> 5] = s; sh[8 + (tid >> 5)] = sq; }
    __syncthreads();
    if (tid < 32) {
        float a  = (tid < 8) ? sh[tid]     : 0.f;
        float b2 = (tid < 8) ? sh[8 + tid] : 0.f;
        #pragma unroll
        for (int m = 4; m; m >>= 1) {
            a  += __shfl_xor_sync(0xffffffffu, a,  m);
            b2 += __shfl_xor_sync(0xffffffffu, b2, m);
        }
        if (tid == 0) { sh[0] = a; sh[8] = b2; }
    }
    __syncthreads();
    float mu  = sh[0] * (1.f / DM);
    float var = sh[8] * (1.f / DM) - mu * mu;
    float inv = rsqrtf(var + 1e-5f);
    float* ur = g_u + (size_t)row * DM;
    ur[tid]       = (v0 - mu) * inv * w[tid]       + bb[tid];
    ur[tid + 256] = (v1 - mu) * inv * w[tid + 256] + bb[tid + 256];
    ur[tid + 512] = (v2 - mu) * inv * w[tid + 512] + bb[tid + 512];
}

// ---------------- NT GEMM: C[M,N] = A[M,K] * B[N,K]^T  (+ optional residual) -
// 128x128x16 tile, 256 threads, 8x8 per thread.
__global__ void __launch_bounds__(256)
k_gemm(const float* __restrict__ A, const float* __restrict__ B,
       float* __restrict__ C, const float* __restrict__ R,
       int M, int N, int K) {
    __shared__ float As[16][128];
    __shared__ float Bs[16][128];
    int bm = blockIdx.y * 128, bn = blockIdx.x * 128;
    int tid = threadIdx.x;
    int lr = tid >> 2;          // 0..63
    int lc = (tid & 3) * 4;     // 0,4,8,12
    int tx = tid & 15, ty = tid >> 4;

    float acc[8][8];
    #pragma unroll
    for (int i = 0; i < 8; i++)
        #pragma unroll
        for (int j = 0; j < 8; j++) acc[i][j] = 0.f;

    for (int k0 = 0; k0 < K; k0 += 16) {
        #pragma unroll
        for (int r = 0; r < 2; r++) {
            int m = bm + lr + 64 * r;
            float4 va = *(const float4*)(A + (size_t)m * K + k0 + lc);
            As[lc + 0][lr + 64 * r] = va.x;
            As[lc + 1][lr + 64 * r] = va.y;
            As[lc + 2][lr + 64 * r] = va.z;
            As[lc + 3][lr + 64 * r] = va.w;
            int n = bn + lr + 64 * r;
            float4 vb = make_float4(0.f, 0.f, 0.f, 0.f);
            if (n < N) vb = *(const float4*)(B + (size_t)n * K + k0 + lc);
            Bs[lc + 0][lr + 64 * r] = vb.x;
            Bs[lc + 1][lr + 64 * r] = vb.y;
            Bs[lc + 2][lr + 64 * r] = vb.z;
            Bs[lc + 3][lr + 64 * r] = vb.w;
        }
        __syncthreads();
        #pragma unroll
        for (int k = 0; k < 16; k++) {
            float4 a0 = *(const float4*)&As[k][ty * 8];
            float4 a1 = *(const float4*)&As[k][ty * 8 + 4];
            float4 b0 = *(const float4*)&Bs[k][tx * 8];
            float4 b1 = *(const float4*)&Bs[k][tx * 8 + 4];
            float ra[8] = {a0.x, a0.y, a0.z, a0.w, a1.x, a1.y, a1.z, a1.w};
            float rb[8] = {b0.x, b0.y, b0.z, b0.w, b1.x, b1.y, b1.z, b1.w};
            #pragma unroll
            for (int i = 0; i < 8; i++)
                #pragma unroll
                for (int j = 0; j < 8; j++)
                    acc[i][j] += ra[i] * rb[j];
        }
        __syncthreads();
    }
    #pragma unroll
    for (int i = 0; i < 8; i++) {
        int m = bm + ty * 8 + i;
        if (m >= M) continue;
        #pragma unroll
        for (int j = 0; j < 8; j++) {
            int n = bn + tx * 8 + j;
            if (n < N) {
                float v = acc[i][j];
                if (R) v += R[(size_t)m * N + n];
                C[(size_t)m * N + n] = v;
            }
        }
    }
}

// ---------------- dt = softplus(raw + bias), dA = exp(dt * -exp(A_log)) -----
__global__ void k_dtda(const float* __restrict__ dtb, const float* __restrict__ alog) {
    int i = blockIdx.x * 256 + threadIdx.x;
    if (i >= TT * NH) return;
    int h = i % NH, t = i / NH;
    float xv = g_zx[(size_t)t * DP + (DI + CD) + h] + dtb[h];
    float dt = (xv > 20.f) ? xv : log1pf(expf(xv));
    float A = -expf(alog[h]);
    g_dt[i] = dt;
    g_dA[i] = expf(dt * A);
}

// ---------------- causal depthwise conv(4) + bias + SiLU --------------------
__global__ void k_conv(const float* __restrict__ cw, const float* __restrict__ cb) {
    int i = blockIdx.x * 256 + threadIdx.x;
    if (i >= TT * CD) return;
    int c = i % CD, t = i / CD, b = t / LEN, l = t % LEN;
    float acc = cb[c];
    #pragma unroll
    for (int k = 0; k < 4; k++) {
        int ll = l - 3 + k;
        if (ll >= 0)
            acc += g_zx[((size_t)(b * LEN + ll)) * DP + DI + c] * cw[c * 4 + k];
    }
    g_xbc[(size_t)t * CD + c] = acc / (1.f + expf(-acc));
}

// ---------------- scan phase 1: per-chunk local final state + decay product -
__global__ void k_scan1() {
    int c = blockIdx.x, hd = blockIdx.y, b = blockIdx.z;
    int tid = threadIdx.x;
    __shared__ float sx[CH * HD];
    __shared__ float sB[CH * DS];
    __shared__ float sdt[CH];
    __shared__ float sdA[CH];
    int t0 = c * CH;
    size_t rb = ((size_t)(b * LEN + t0)) * CD;
    for (int idx = tid; idx < CH * HD; idx += 256) {
        int t = idx >> 6, p = idx & 63;
        sx[idx] = g_xbc[rb + (size_t)t * CD + hd * HD + p];
    }
    for (int idx = tid; idx < CH * DS; idx += 256) {
        int t = idx >> 4, n = idx & 15;
        sB[idx] = g_xbc[rb + (size_t)t * CD + DI + n];
    }
    for (int idx = tid; idx < CH; idx += 256) {
        int tg = (b * LEN + t0 + idx) * NH + hd;
        sdt[idx] = g_dt[tg];
        sdA[idx] = g_dA[tg];
    }
    __syncthreads();
    int n = tid & 15, pg = tid >> 4;
    float h0 = 0.f, h1 = 0.f, h2 = 0.f, h3 = 0.f, run = 1.f;
    for (int t = 0; t < CH; t++) {
        float dA = sdA[t];
        float coef = sdt[t] * sB[t * DS + n];
        run *= dA;
        h0 = dA * h0 + coef * sx[t * HD + pg];
        h1 = dA * h1 + coef * sx[t * HD + pg + 16];
        h2 = dA * h2 + coef * sx[t * HD + pg + 32];
        h3 = dA * h3 + coef * sx[t * HD + pg + 48];
    }
    size_t base = ((size_t)((b * NH + hd) * NC + c)) * (HD * DS);
    g_hl[base + (pg)      * DS + n] = h0;
    g_hl[base + (pg + 16) * DS + n] = h1;
    g_hl[base + (pg + 32) * DS + n] = h2;
    g_hl[base + (pg + 48) * DS + n] = h3;
    if (tid == 0) g_P[(b * NH + hd) * NC + c] = run;
}

// ---------------- scan phase 2: inter-chunk combine (48 blocks, sequential) -
__global__ void k_scan2() {
    int bh = blockIdx.x, tid = threadIdx.x;
    float H0 = 0.f, H1 = 0.f, H2 = 0.f, H3 = 0.f;
    for (int c = 0; c < NC; c++) {
        size_t base = ((size_t)(bh * NC + c)) * (HD * DS);
        float P = g_P[bh * NC + c];
        g_hs[base + tid]       = H0;
        g_hs[base + tid + 256] = H1;
        g_hs[base + tid + 512] = H2;
        g_hs[base + tid + 768] = H3;
        H0 = P * H0 + g_hl[base + tid];
        H1 = P * H1 + g_hl[base + tid + 256];
        H2 = P * H2 + g_hl[base + tid + 512];
        H3 = P * H3 + g_hl[base + tid + 768];
    }
}

// ---------------- scan phase 3: full scan w/ correct init, emit y -----------
__global__ void k_scan3(const float* __restrict__ Dp) {
    int c = blockIdx.x, hd = blockIdx.y, b = blockIdx.z;
    int tid = threadIdx.x;
    __shared__ float sx[CH * HD];
    __shared__ float sB[CH * DS];
    __shared__ float sC[CH * DS];
    __shared__ float sdt[CH];
    __shared__ float sdA[CH];
    int t0 = c * CH;
    size_t rb = ((size_t)(b * LEN + t0)) * CD;
    for (int idx = tid; idx < CH * HD; idx += 256) {
        int t = idx >> 6, p = idx & 63;
        sx[idx] = g_xbc[rb + (size_t)t * CD + hd * HD + p];
    }
    for (int idx = tid; idx < CH * DS; idx += 256) {
        int t = idx >> 4, n = idx & 15;
        sB[idx] = g_xbc[rb + (size_t)t * CD + DI + n];
        sC[idx] = g_xbc[rb + (size_t)t * CD + DI + DS + n];
    }
    for (int idx = tid; idx < CH; idx += 256) {
        int tg = (b * LEN + t0 + idx) * NH + hd;
        sdt[idx] = g_dt[tg];
        sdA[idx] = g_dA[tg];
    }
    __syncthreads();
    int n = tid & 15, pg = tid >> 4;
    size_t base = ((size_t)((b * NH + hd) * NC + c)) * (HD * DS);
    float h0 = g_hs[base + (pg)      * DS + n];
    float h1 = g_hs[base + (pg + 16) * DS + n];
    float h2 = g_hs[base + (pg + 32) * DS + n];
    float h3 = g_hs[base + (pg + 48) * DS + n];
    float Dh = Dp[hd];
    for (int t = 0; t < CH; t++) {
        float dA = sdA[t];
        float coef = sdt[t] * sB[t * DS + n];
        float x0 = sx[t * HD + pg];
        float x1 = sx[t * HD + pg + 16];
        float x2 = sx[t * HD + pg + 32];
        float x3 = sx[t * HD + pg + 48];
        h0 = dA * h0 + coef * x0;
        h1 = dA * h1 + coef * x1;
        h2 = dA * h2 + coef * x2;
        h3 = dA * h3 + coef * x3;
        float Ct = sC[t * DS + n];
        float y0 = h0 * Ct, y1 = h1 * Ct, y2 = h2 * Ct, y3 = h3 * Ct;
        #pragma unroll
        for (int m = 1; m < 16; m <<= 1) {
            y0 += __shfl_xor_sync(0xffffffffu, y0, m);
            y1 += __shfl_xor_sync(0xffffffffu, y1, m);
            y2 += __shfl_xor_sync(0xffffffffu, y2, m);
            y3 += __shfl_xor_sync(0xffffffffu, y3, m);
        }
        if (n == 0) {
            float* yr = g_y + ((size_t)(b * LEN + t0 + t)) * DI + hd * HD;
            yr[pg]      = y0 + Dh * x0;
            yr[pg + 16] = y1 + Dh * x1;
            yr[pg + 32] = y2 + Dh * x2;
            yr[pg + 48] = y3 + Dh * x3;
        }
    }
}

// ---------------- gating + RMSNorm: one block per token row -----------------
__global__ void k_gate(const float* __restrict__ gnw) {
    int row = blockIdx.x, tid = threadIdx.x;
    const float* yr = g_y  + (size_t)row * DI;
    const float* zr = g_zx + (size_t)row * DP;  // z = first DI columns
    float gv[6];
    float sq = 0.f;
    #pragma unroll
    for (int i = 0; i < 6; i++) {
        int cc = tid + 256 * i;
        float z = zr[cc];
        float g = yr[cc] * (z / (1.f + expf(-z)));
        gv[i] = g;
        sq += g * g;
    }
    __shared__ float sh[8];
    #pragma unroll
    for (int m = 16; m; m >>= 1) sq += __shfl_xor_sync(0xffffffffu, sq, m);
    if ((tid & 31) == 0) sh[tid >> 5] = sq;
    __syncthreads();
    if (tid < 32) {
        float a = (tid < 8) ? sh[tid] : 0.f;
        #pragma unroll
        for (int m = 4; m; m >>= 1) a += __shfl_xor_sync(0xffffffffu, a, m);
        if (tid == 0) sh[0] = a;
    }
    __syncthreads();
    float inv = rsqrtf(sh[0] * (1.f / DI) + 1e-5f);
    float* gr = g_g + (size_t)row * DI;
    #pragma unroll
    for (int i = 0; i < 6; i++) {
        int cc = tid + 256 * i;
        gr[cc] = gv[i] * inv * gnw[cc];
    }
}

// ---------------- launcher ---------------------------------------------------
extern "C" void kernel_launch(void* const* d_in, const int* in_sizes, int n_in,
                              void* d_out, int out_size) {
    const float* x       = (const float*)d_in[0];
    const float* ln_w    = (const float*)d_in[1];
    const float* ln_b    = (const float*)d_in[2];
    const float* W_in    = (const float*)d_in[3];
    const float* conv_w  = (const float*)d_in[4];
    const float* conv_b  = (const float*)d_in[5];
    const float* dt_bias = (const float*)d_in[6];
    const float* A_log   = (const float*)d_in[7];
    const float* Dv      = (const float*)d_in[8];
    const float* gnw     = (const float*)d_in[9];
    const float* W_out   = (const float*)d_in[10];
    float* out = (float*)d_out;

    float *pu, *pzx, *pg;
    cudaGetSymbolAddress((void**)&pu,  g_u);
    cudaGetSymbolAddress((void**)&pzx, g_zx);
    cudaGetSymbolAddress((void**)&pg,  g_g);

    k_ln<<<TT, 256>>>(x, ln_w, ln_b);
    k_gemm<<<dim3((DP + 127) / 128, TT / 128), 256>>>(pu, W_in, pzx, nullptr, TT, DP, DM);
    k_dtda<<<(TT * NH + 255) / 256, 256>>>(dt_bias, A_log);
    k_conv<<<(TT * CD + 255) / 256, 256>>>(conv_w, conv_b);
    k_scan1<<<dim3(NC, NH, BSZ), 256>>>();
    k_scan2<<<BSZ * NH, 256>>>();
    k_scan3<<<dim3(NC, NH, BSZ), 256>>>(Dv);
    k_gate<<<TT, 256>>>(gnw);
    k_gemm<<<dim3((DM + 127) / 128, TT / 128), 256>>>(pg, W_out, out, x, TT, DM, DI);
}

// round 2
// speedup vs baseline: 1.8015x; 1.8015x over previous
#include <cuda_runtime.h>
#include <cuda_bf16.h>
#include <math.h>

#define BSZ 2
#define LEN 4096
#define TT (BSZ*LEN)          // 8192 tokens
#define DM 768
#define DI 1536
#define DS 16
#define NH 24
#define HD 64
#define CD 1568               // DI + 2*DS
#define DP 3128               // 2*DI + 2*DS + NH
#define NC 64                 // chunks
#define CH 64                 // chunk length (LEN/NC)

// ---------------- scratch (static device arrays; no runtime alloc) ----------
__device__ float g_u[TT*DM];
__device__ float g_zx[(size_t)TT*DP];
__device__ float g_xbc[(size_t)TT*CD];
__device__ float g_dt[TT*NH];
__device__ float g_dA[TT*NH];
__device__ float g_y[(size_t)TT*DI];
__device__ float g_g[(size_t)TT*DI];
__device__ float g_hl[BSZ*NH*NC*HD*DS];
__device__ float g_hs[BSZ*NH*NC*HD*DS];
__device__ float g_P[BSZ*NH*NC];

// ---------------- layernorm: one block per token row ------------------------
__global__ void k_ln(const float* __restrict__ x, const float* __restrict__ w,
                     const float* __restrict__ bb) {
    int row = blockIdx.x;
    int tid = threadIdx.x;
    const float* xr = x + (size_t)row * DM;
    float v0 = xr[tid], v1 = xr[tid + 256], v2 = xr[tid + 512];
    float s  = v0 + v1 + v2;
    float sq = v0*v0 + v1*v1 + v2*v2;
    __shared__ float sh[16];
    #pragma unroll
    for (int m = 16; m; m >>= 1) {
        s  += __shfl_xor_sync(0xffffffffu, s,  m);
        sq += __shfl_xor_sync(0xffffffffu, sq, m);
    }
    if ((tid & 31) == 0) { sh[tid >> 5] = s; sh[8 + (tid >> 5)] = sq; }
    __syncthreads();
    if (tid < 32) {
        float a  = (tid < 8) ? sh[tid]     : 0.f;
        float b2 = (tid < 8) ? sh[8 + tid] : 0.f;
        #pragma unroll
        for (int m = 4; m; m >>= 1) {
            a  += __shfl_xor_sync(0xffffffffu, a,  m);
            b2 += __shfl_xor_sync(0xffffffffu, b2, m);
        }
        if (tid == 0) { sh[0] = a; sh[8] = b2; }
    }
    __syncthreads();
    float mu  = sh[0] * (1.f / DM);
    float var = sh[8] * (1.f / DM) - mu * mu;
    float inv = rsqrtf(var + 1e-5f);
    float* ur = g_u + (size_t)row * DM;
    ur[tid]       = (v0 - mu) * inv * w[tid]       + bb[tid];
    ur[tid + 256] = (v1 - mu) * inv * w[tid + 256] + bb[tid + 256];
    ur[tid + 512] = (v2 - mu) * inv * w[tid + 512] + bb[tid + 512];
}

// ============================================================================
// Tensor-core NT GEMM: C[M,N] = A[M,K] * B[N,K]^T (+ optional residual R)
// bf16 hi/lo split (3 HMMA passes) for fp32-level accuracy.
// Tile 128x128x16, 8 warps, each warp computes 64x32 via m16n8k16.
// Requirements: M % 128 == 0, K % 16 == 0. N arbitrary (bounds-checked).
// ============================================================================
#define SPITCH 24   // smem row pitch in bf16 elems (16 data + 8 pad) -> conflict-free

__device__ __forceinline__ unsigned pk2(float a, float b) {
    __nv_bfloat162 t = __floats2bfloat162_rn(a, b);
    return *(unsigned*)&t;
}
__device__ __forceinline__ unsigned ldu(const __nv_bfloat16* p) {
    return *(const unsigned*)p;
}
__device__ __forceinline__ void cvt_store(float4 v, __nv_bfloat16* ph, __nv_bfloat16* pl) {
    float hx = __bfloat162float(__float2bfloat16_rn(v.x));
    float hy = __bfloat162float(__float2bfloat16_rn(v.y));
    float hz = __bfloat162float(__float2bfloat16_rn(v.z));
    float hw = __bfloat162float(__float2bfloat16_rn(v.w));
    uint2 H, L;
    H.x = pk2(v.x, v.y); H.y = pk2(v.z, v.w);
    L.x = pk2(v.x - hx, v.y - hy); L.y = pk2(v.z - hz, v.w - hw);
    *(uint2*)ph = H;
    *(uint2*)pl = L;
}

#define MMA_BF16(d, a, b) \
  asm volatile("mma.sync.aligned.m16n8k16.row.col.f32.bf16.bf16.f32 " \
      "{%0,%1,%2,%3}, {%4,%5,%6,%7}, {%8,%9}, {%0,%1,%2,%3};\n" \
      : "+f"(d[0]), "+f"(d[1]), "+f"(d[2]), "+f"(d[3]) \
      : "r"(a[0]), "r"(a[1]), "r"(a[2]), "r"(a[3]), "r"(b[0]), "r"(b[1]))

__global__ void __launch_bounds__(256, 1)
k_gemm_tc(const float* __restrict__ A, const float* __restrict__ B,
          float* __restrict__ C, const float* __restrict__ R,
          int M, int N, int K) {
    __shared__ __align__(16) __nv_bfloat16 sAh[2][128][SPITCH];
    __shared__ __align__(16) __nv_bfloat16 sAl[2][128][SPITCH];
    __shared__ __align__(16) __nv_bfloat16 sBh[2][128][SPITCH];
    __shared__ __align__(16) __nv_bfloat16 sBl[2][128][SPITCH];

    const int tid = threadIdx.x;
    const int warp = tid >> 5, lane = tid & 31;
    const int g = lane >> 2, q = lane & 3;        // mma group / quad
    const int wm = (warp & 1) * 64;                // warp m offset
    const int wn = (warp >> 1) * 32;               // warp n offset
    const int bm = blockIdx.y * 128, bn = blockIdx.x * 128;

    const int i0 = tid, i1 = tid + 256;
    const int ar0 = i0 >> 2, ar1 = i1 >> 2;        // rows 0..63 / 64..127
    const int kq0 = (i0 & 3) << 2, kq1 = (i1 & 3) << 2;

    float acc[4][4][4];
    #pragma unroll
    for (int i = 0; i < 4; i++)
        #pragma unroll
        for (int j = 0; j < 4; j++)
            #pragma unroll
            for (int k = 0; k < 4; k++) acc[i][j][k] = 0.f;

    const int nIter = K / 16;

    // --- stage 0 load ---
    {
        float4 a0 = *(const float4*)(A + (size_t)(bm + ar0) * K + kq0);
        float4 a1 = *(const float4*)(A + (size_t)(bm + ar1) * K + kq1);
        float4 b0 = make_float4(0.f,0.f,0.f,0.f), b1 = b0;
        if (bn + ar0 < N) b0 = *(const float4*)(B + (size_t)(bn + ar0) * K + kq0);
        if (bn + ar1 < N) b1 = *(const float4*)(B + (size_t)(bn + ar1) * K + kq1);
        cvt_store(a0, &sAh[0][ar0][kq0], &sAl[0][ar0][kq0]);
        cvt_store(a1, &sAh[0][ar1][kq1], &sAl[0][ar1][kq1]);
        cvt_store(b0, &sBh[0][ar0][kq0], &sBl[0][ar0][kq0]);
        cvt_store(b1, &sBh[0][ar1][kq1], &sBl[0][ar1][kq1]);
    }
    __syncthreads();

    for (int kt = 0; kt < nIter; kt++) {
        int s = kt & 1;
        // prefetch next k-slab into registers
        float4 na0, na1, nb0, nb1;
        bool have = (kt + 1) < nIter;
        if (have) {
            int k0 = (kt + 1) * 16;
            na0 = *(const float4*)(A + (size_t)(bm + ar0) * K + k0 + kq0);
            na1 = *(const float4*)(A + (size_t)(bm + ar1) * K + k0 + kq1);
            nb0 = make_float4(0.f,0.f,0.f,0.f); nb1 = nb0;
            if (bn + ar0 < N) nb0 = *(const float4*)(B + (size_t)(bn + ar0) * K + k0 + kq0);
            if (bn + ar1 < N) nb1 = *(const float4*)(B + (size_t)(bn + ar1) * K + k0 + kq1);
        }

        // --- compute current stage ---
        const __nv_bfloat16* aH = &sAh[s][wm + g][2 * q];
        const __nv_bfloat16* aL = &sAl[s][wm + g][2 * q];
        const __nv_bfloat16* bH = &sBh[s][wn + g][2 * q];
        const __nv_bfloat16* bL = &sBl[s][wn + g][2 * q];

        unsigned ah[4][4], al[4][4], bh[4][2], bl[4][2];
        #pragma unroll
        for (int mt = 0; mt < 4; mt++) {
            int r = mt * 16 * SPITCH;
            ah[mt][0] = ldu(aH + r);
            ah[mt][1] = ldu(aH + r + 8 * SPITCH);
            ah[mt][2] = ldu(aH + r + 8);
            ah[mt][3] = ldu(aH + r + 8 * SPITCH + 8);
            al[mt][0] = ldu(aL + r);
            al[mt][1] = ldu(aL + r + 8 * SPITCH);
            al[mt][2] = ldu(aL + r + 8);
            al[mt][3] = ldu(aL + r + 8 * SPITCH + 8);
        }
        #pragma unroll
        for (int nt = 0; nt < 4; nt++) {
            int r = nt * 8 * SPITCH;
            bh[nt][0] = ldu(bH + r);
            bh[nt][1] = ldu(bH + r + 8);
            bl[nt][0] = ldu(bL + r);
            bl[nt][1] = ldu(bL + r + 8);
        }
        #pragma unroll
        for (int mt = 0; mt < 4; mt++)
            #pragma unroll
            for (int nt = 0; nt < 4; nt++) {
                MMA_BF16(acc[mt][nt], ah[mt], bh[nt]);
                MMA_BF16(acc[mt][nt], ah[mt], bl[nt]);
                MMA_BF16(acc[mt][nt], al[mt], bh[nt]);
            }

        if (have) {
            int sn = s ^ 1;
            cvt_store(na0, &sAh[sn][ar0][kq0], &sAl[sn][ar0][kq0]);
            cvt_store(na1, &sAh[sn][ar1][kq1], &sAl[sn][ar1][kq1]);
            cvt_store(nb0, &sBh[sn][ar0][kq0], &sBl[sn][ar0][kq0]);
            cvt_store(nb1, &sBh[sn][ar1][kq1], &sBl[sn][ar1][kq1]);
            __syncthreads();
        }
    }

    // --- epilogue ---
    #pragma unroll
    for (int mt = 0; mt < 4; mt++) {
        int row0 = bm + wm + mt * 16 + g;
        #pragma unroll
        for (int nt = 0; nt < 4; nt++) {
            int col = bn + wn + nt * 8 + 2 * q;
            if (col < N) {
                float2 v0, v1;
                v0.x = acc[mt][nt][0]; v0.y = acc[mt][nt][1];
                v1.x = acc[mt][nt][2]; v1.y = acc[mt][nt][3];
                if (R) {
                    const float* r0 = R + (size_t)row0 * N + col;
                    const float* r1 = R + (size_t)(row0 + 8) * N + col;
                    v0.x += r0[0]; v0.y += r0[1];
                    v1.x += r1[0]; v1.y += r1[1];
                }
                *(float2*)(C + (size_t)row0 * N + col) = v0;
                *(float2*)(C + (size_t)(row0 + 8) * N + col) = v1;
            }
        }
    }
}

// ---------------- dt = softplus(raw + bias), dA = exp(dt * -exp(A_log)) -----
__global__ void k_dtda(const float* __restrict__ dtb, const float* __restrict__ alog) {
    int i = blockIdx.x * 256 + threadIdx.x;
    if (i >= TT * NH) return;
    int h = i % NH, t = i / NH;
    float xv = g_zx[(size_t)t * DP + (DI + CD) + h] + dtb[h];
    float dt = (xv > 20.f) ? xv : log1pf(expf(xv));
    float A = -expf(alog[h]);
    g_dt[i] = dt;
    g_dA[i] = expf(dt * A);
}

// ---------------- causal depthwise conv(4) + bias + SiLU --------------------
__global__ void k_conv(const float* __restrict__ cw, const float* __restrict__ cb) {
    int i = blockIdx.x * 256 + threadIdx.x;
    if (i >= TT * CD) return;
    int c = i % CD, t = i / CD, b = t / LEN, l = t % LEN;
    float acc = cb[c];
    #pragma unroll
    for (int k = 0; k < 4; k++) {
        int ll = l - 3 + k;
        if (ll >= 0)
            acc += g_zx[((size_t)(b * LEN + ll)) * DP + DI + c] * cw[c * 4 + k];
    }
    g_xbc[(size_t)t * CD + c] = acc / (1.f + expf(-acc));
}

// ---------------- scan phase 1: per-chunk local final state + decay product -
__global__ void k_scan1() {
    int c = blockIdx.x, hd = blockIdx.y, b = blockIdx.z;
    int tid = threadIdx.x;
    __shared__ float sx[CH * HD];
    __shared__ float sB[CH * DS];
    __shared__ float sdt[CH];
    __shared__ float sdA[CH];
    int t0 = c * CH;
    size_t rb = ((size_t)(b * LEN + t0)) * CD;
    for (int idx = tid; idx < CH * HD; idx += 256) {
        int t = idx >> 6, p = idx & 63;
        sx[idx] = g_xbc[rb + (size_t)t * CD + hd * HD + p];
    }
    for (int idx = tid; idx < CH * DS; idx += 256) {
        int t = idx >> 4, n = idx & 15;
        sB[idx] = g_xbc[rb + (size_t)t * CD + DI + n];
    }
    for (int idx = tid; idx < CH; idx += 256) {
        int tg = (b * LEN + t0 + idx) * NH + hd;
        sdt[idx] = g_dt[tg];
        sdA[idx] = g_dA[tg];
    }
    __syncthreads();
    int n = tid & 15, pg = tid >> 4;
    float h0 = 0.f, h1 = 0.f, h2 = 0.f, h3 = 0.f, run = 1.f;
    for (int t = 0; t < CH; t++) {
        float dA = sdA[t];
        float coef = sdt[t] * sB[t * DS + n];
        run *= dA;
        h0 = dA * h0 + coef * sx[t * HD + pg];
        h1 = dA * h1 + coef * sx[t * HD + pg + 16];
        h2 = dA * h2 + coef * sx[t * HD + pg + 32];
        h3 = dA * h3 + coef * sx[t * HD + pg + 48];
    }
    size_t base = ((size_t)((b * NH + hd) * NC + c)) * (HD * DS);
    g_hl[base + (pg)      * DS + n] = h0;
    g_hl[base + (pg + 16) * DS + n] = h1;
    g_hl[base + (pg + 32) * DS + n] = h2;
    g_hl[base + (pg + 48) * DS + n] = h3;
    if (tid == 0) g_P[(b * NH + hd) * NC + c] = run;
}

// ---------------- scan phase 2: inter-chunk combine (48 blocks, sequential) -
__global__ void k_scan2() {
    int bh = blockIdx.x, tid = threadIdx.x;
    float H0 = 0.f, H1 = 0.f, H2 = 0.f, H3 = 0.f;
    for (int c = 0; c < NC; c++) {
        size_t base = ((size_t)(bh * NC + c)) * (HD * DS);
        float P = g_P[bh * NC + c];
        g_hs[base + tid]       = H0;
        g_hs[base + tid + 256] = H1;
        g_hs[base + tid + 512] = H2;
        g_hs[base + tid + 768] = H3;
        H0 = P * H0 + g_hl[base + tid];
        H1 = P * H1 + g_hl[base + tid + 256];
        H2 = P * H2 + g_hl[base + tid + 512];
        H3 = P * H3 + g_hl[base + tid + 768];
    }
}

// ---------------- scan phase 3: full scan w/ correct init, emit y -----------
__global__ void k_scan3(const float* __restrict__ Dp) {
    int c = blockIdx.x, hd = blockIdx.y, b = blockIdx.z;
    int tid = threadIdx.x;
    __shared__ float sx[CH * HD];
    __shared__ float sB[CH * DS];
    __shared__ float sC[CH * DS];
    __shared__ float sdt[CH];
    __shared__ float sdA[CH];
    int t0 = c * CH;
    size_t rb = ((size_t)(b * LEN + t0)) * CD;
    for (int idx = tid; idx < CH * HD; idx += 256) {
        int t = idx >> 6, p = idx & 63;
        sx[idx] = g_xbc[rb + (size_t)t * CD + hd * HD + p];
    }
    for (int idx = tid; idx < CH * DS; idx += 256) {
        int t = idx >> 4, n = idx & 15;
        sB[idx] = g_xbc[rb + (size_t)t * CD + DI + n];
        sC[idx] = g_xbc[rb + (size_t)t * CD + DI + DS + n];
    }
    for (int idx = tid; idx < CH; idx += 256) {
        int tg = (b * LEN + t0 + idx) * NH + hd;
        sdt[idx] = g_dt[tg];
        sdA[idx] = g_dA[tg];
    }
    __syncthreads();
    int n = tid & 15, pg = tid >> 4;
    size_t base = ((size_t)((b * NH + hd) * NC + c)) * (HD * DS);
    float h0 = g_hs[base + (pg)      * DS + n];
    float h1 = g_hs[base + (pg + 16) * DS + n];
    float h2 = g_hs[base + (pg + 32) * DS + n];
    float h3 = g_hs[base + (pg + 48) * DS + n];
    float Dh = Dp[hd];
    for (int t = 0; t < CH; t++) {
        float dA = sdA[t];
        float coef = sdt[t] * sB[t * DS + n];
        float x0 = sx[t * HD + pg];
        float x1 = sx[t * HD + pg + 16];
        float x2 = sx[t * HD + pg + 32];
        float x3 = sx[t * HD + pg + 48];
        h0 = dA * h0 + coef * x0;
        h1 = dA * h1 + coef * x1;
        h2 = dA * h2 + coef * x2;
        h3 = dA * h3 + coef * x3;
        float Ct = sC[t * DS + n];
        float y0 = h0 * Ct, y1 = h1 * Ct, y2 = h2 * Ct, y3 = h3 * Ct;
        #pragma unroll
        for (int m = 1; m < 16; m <<= 1) {
            y0 += __shfl_xor_sync(0xffffffffu, y0, m);
            y1 += __shfl_xor_sync(0xffffffffu, y1, m);
            y2 += __shfl_xor_sync(0xffffffffu, y2, m);
            y3 += __shfl_xor_sync(0xffffffffu, y3, m);
        }
        if (n == 0) {
            float* yr = g_y + ((size_t)(b * LEN + t0 + t)) * DI + hd * HD;
            yr[pg]      = y0 + Dh * x0;
            yr[pg + 16] = y1 + Dh * x1;
            yr[pg + 32] = y2 + Dh * x2;
            yr[pg + 48] = y3 + Dh * x3;
        }
    }
}

// ---------------- gating + RMSNorm: one block per token row -----------------
__global__ void k_gate(const float* __restrict__ gnw) {
    int row = blockIdx.x, tid = threadIdx.x;
    const float* yr = g_y  + (size_t)row * DI;
    const float* zr = g_zx + (size_t)row * DP;  // z = first DI columns
    float gv[6];
    float sq = 0.f;
    #pragma unroll
    for (int i = 0; i < 6; i++) {
        int cc = tid + 256 * i;
        float z = zr[cc];
        float g = yr[cc] * (z / (1.f + expf(-z)));
        gv[i] = g;
        sq += g * g;
    }
    __shared__ float sh[8];
    #pragma unroll
    for (int m = 16; m; m >>= 1) sq += __shfl_xor_sync(0xffffffffu, sq, m);
    if ((tid & 31) == 0) sh[tid >> 5] = sq;
    __syncthreads();
    if (tid < 32) {
        float a = (tid < 8) ? sh[tid] : 0.f;
        #pragma unroll
        for (int m = 4; m; m >>= 1) a += __shfl_xor_sync(0xffffffffu, a, m);
        if (tid == 0) sh[0] = a;
    }
    __syncthreads();
    float inv = rsqrtf(sh[0] * (1.f / DI) + 1e-5f);
    float* gr = g_g + (size_t)row * DI;
    #pragma unroll
    for (int i = 0; i < 6; i++) {
        int cc = tid + 256 * i;
        gr[cc] = gv[i] * inv * gnw[cc];
    }
}

// ---------------- launcher ---------------------------------------------------
extern "C" void kernel_launch(void* const* d_in, const int* in_sizes, int n_in,
                              void* d_out, int out_size) {
    const float* x       = (const float*)d_in[0];
    const float* ln_w    = (const float*)d_in[1];
    const float* ln_b    = (const float*)d_in[2];
    const float* W_in    = (const float*)d_in[3];
    const float* conv_w  = (const float*)d_in[4];
    const float* conv_b  = (const float*)d_in[5];
    const float* dt_bias = (const float*)d_in[6];
    const float* A_log   = (const float*)d_in[7];
    const float* Dv      = (const float*)d_in[8];
    const float* gnw     = (const float*)d_in[9];
    const float* W_out   = (const float*)d_in[10];
    float* out = (float*)d_out;

    float *pu, *pzx, *pg;
    cudaGetSymbolAddress((void**)&pu,  g_u);
    cudaGetSymbolAddress((void**)&pzx, g_zx);
    cudaGetSymbolAddress((void**)&pg,  g_g);

    k_ln<<<TT, 256>>>(x, ln_w, ln_b);
    k_gemm_tc<<<dim3((DP + 127) / 128, TT / 128), 256>>>(pu, W_in, pzx, nullptr, TT, DP, DM);
    k_dtda<<<(TT * NH + 255) / 256, 256>>>(dt_bias, A_log);
    k_conv<<<(TT * CD + 255) / 256, 256>>>(conv_w, conv_b);
    k_scan1<<<dim3(NC, NH, BSZ), 256>>>();
    k_scan2<<<BSZ * NH, 256>>>();
    k_scan3<<<dim3(NC, NH, BSZ), 256>>>(Dv);
    k_gate<<<TT, 256>>>(gnw);
    k_gemm_tc<<<dim3((DM + 127) / 128, TT / 128), 256>>>(pg, W_out, out, x, TT, DM, DI);
}

// round 3
// speedup vs baseline: 2.1896x; 1.2154x over previous
#include <cuda_runtime.h>
#include <cuda_bf16.h>
#include <math.h>
#include <stdint.h>

#define BSZ 2
#define LEN 4096
#define TT (BSZ*LEN)          // 8192 tokens
#define DM 768
#define DI 1536
#define DS 16
#define NH 24
#define HD 64
#define CD 1568               // DI + 2*DS
#define DP 3128               // 2*DI + 2*DS + NH
#define NP1 3200              // DP padded to 128
#define NC 64                 // chunks
#define CH 64                 // chunk length (LEN/NC)

// ---------------- scratch (static device arrays; no runtime alloc) ----------
__device__ float g_zx[(size_t)TT*DP];
__device__ float g_xbc[(size_t)TT*CD];
__device__ float g_dt[TT*NH];
__device__ float g_dA[TT*NH];
__device__ float g_y[(size_t)TT*DI];
__device__ float g_hl[BSZ*NH*NC*HD*DS];
__device__ float g_hs[BSZ*NH*NC*HD*DS];
__device__ float g_P[BSZ*NH*NC];
// bf16 hi/lo operand buffers
__device__ __nv_bfloat16 g_uh[(size_t)TT*DM];
__device__ __nv_bfloat16 g_ul[(size_t)TT*DM];
__device__ __nv_bfloat16 g_W1h[(size_t)NP1*DM];
__device__ __nv_bfloat16 g_W1l[(size_t)NP1*DM];
__device__ __nv_bfloat16 g_gh[(size_t)TT*DI];
__device__ __nv_bfloat16 g_gl[(size_t)TT*DI];
__device__ __nv_bfloat16 g_W2h[(size_t)DM*DI];
__device__ __nv_bfloat16 g_W2l[(size_t)DM*DI];

__device__ __forceinline__ void split1(float v, __nv_bfloat16* ph, __nv_bfloat16* pl) {
    __nv_bfloat16 h = __float2bfloat16_rn(v);
    *ph = h;
    *pl = __float2bfloat16_rn(v - __bfloat162float(h));
}

// ---------------- weight split: W[rows*cols] -> H/L[rowsPad*cols] -----------
__global__ void k_split(const float* __restrict__ W, __nv_bfloat16* __restrict__ H,
                        __nv_bfloat16* __restrict__ L, int n, int nPad) {
    int i = blockIdx.x * 256 + threadIdx.x;
    if (i >= nPad) return;
    float v = (i < n) ? W[i] : 0.f;
    split1(v, H + i, L + i);
}

// ---------------- layernorm: one block per token row, emits bf16 hi/lo ------
__global__ void k_ln(const float* __restrict__ x, const float* __restrict__ w,
                     const float* __restrict__ bb) {
    int row = blockIdx.x;
    int tid = threadIdx.x;
    const float* xr = x + (size_t)row * DM;
    float v0 = xr[tid], v1 = xr[tid + 256], v2 = xr[tid + 512];
    float s  = v0 + v1 + v2;
    float sq = v0*v0 + v1*v1 + v2*v2;
    __shared__ float sh[16];
    #pragma unroll
    for (int m = 16; m; m >>= 1) {
        s  += __shfl_xor_sync(0xffffffffu, s,  m);
        sq += __shfl_xor_sync(0xffffffffu, sq, m);
    }
    if ((tid & 31) == 0) { sh[tid >> 5] = s; sh[8 + (tid >> 5)] = sq; }
    __syncthreads();
    if (tid < 32) {
        float a  = (tid < 8) ? sh[tid]     : 0.f;
        float b2 = (tid < 8) ? sh[8 + tid] : 0.f;
        #pragma unroll
        for (int m = 4; m; m >>= 1) {
            a  += __shfl_xor_sync(0xffffffffu, a,  m);
            b2 += __shfl_xor_sync(0xffffffffu, b2, m);
        }
        if (tid == 0) { sh[0] = a; sh[8] = b2; }
    }
    __syncthreads();
    float mu  = sh[0] * (1.f / DM);
    float var = sh[8] * (1.f / DM) - mu * mu;
    float inv = rsqrtf(var + 1e-5f);
    size_t base = (size_t)row * DM;
    float u0 = (v0 - mu) * inv * w[tid]       + bb[tid];
    float u1 = (v1 - mu) * inv * w[tid + 256] + bb[tid + 256];
    float u2 = (v2 - mu) * inv * w[tid + 512] + bb[tid + 512];
    split1(u0, g_uh + base + tid,       g_ul + base + tid);
    split1(u1, g_uh + base + tid + 256, g_ul + base + tid + 256);
    split1(u2, g_uh + base + tid + 512, g_ul + base + tid + 512);
}

// ============================================================================
// Tensor-core NT GEMM with pre-split bf16 hi/lo operands.
// C[M,N] = (Ah+Al)[M,K] * (Bh+Bl)[N,K]^T (3-pass, lo*lo dropped), + residual.
// Tile 128x128x32, 8 warps, 3-stage cp.async, ldmatrix.x4.
// M%128==0, K%32==0, B padded so all loads valid; store bounds col<N.
// ============================================================================
#define SP 40                 // smem row pitch in bf16 (32 data + 8 pad)
#define STG_ELEM (128*SP)     // 5120 bf16 per matrix
#define STAGE_B (4*STG_ELEM*2) // bytes per stage (Ah,Al,Bh,Bl)

__device__ __forceinline__ uint32_t smaddr(const void* p) {
    return (uint32_t)__cvta_generic_to_shared(p);
}
#define CPA(d, s) asm volatile("cp.async.cg.shared.global [%0], [%1], 16;\n" :: "r"(d), "l"(s))
#define CPCOMMIT() asm volatile("cp.async.commit_group;\n")
#define CPWAIT1() asm volatile("cp.async.wait_group 1;\n")
#define LDSM4(r0,r1,r2,r3,a) asm volatile( \
    "ldmatrix.sync.aligned.m8n8.x4.shared.b16 {%0,%1,%2,%3}, [%4];\n" \
    : "=r"(r0),"=r"(r1),"=r"(r2),"=r"(r3) : "r"(a))
#define MMA(d, a, b0, b1) \
  asm volatile("mma.sync.aligned.m16n8k16.row.col.f32.bf16.bf16.f32 " \
      "{%0,%1,%2,%3}, {%4,%5,%6,%7}, {%8,%9}, {%0,%1,%2,%3};\n" \
      : "+f"(d[0]), "+f"(d[1]), "+f"(d[2]), "+f"(d[3]) \
      : "r"(a[0]), "r"(a[1]), "r"(a[2]), "r"(a[3]), "r"(b0), "r"(b1))

__global__ void __launch_bounds__(256, 1)
k_gemm_bf(const __nv_bfloat16* __restrict__ Ah, const __nv_bfloat16* __restrict__ Al,
          const __nv_bfloat16* __restrict__ Bh, const __nv_bfloat16* __restrict__ Bl,
          float* __restrict__ C, const float* __restrict__ R,
          int M, int N, int K) {
    extern __shared__ __nv_bfloat16 sm[];
    const int tid = threadIdx.x;
    const int warp = tid >> 5, lane = tid & 31;
    const int wm = (warp & 1) * 64;
    const int wn = (warp >> 1) * 32;
    const int bm = blockIdx.y * 128, bn = blockIdx.x * 128;
    const int nIter = K >> 5;

    // cp.async thread mapping: 2x (row, 8-col chunk)
    const int r0 = tid >> 2;
    const int c0 = (tid & 3) << 3;
    const uint32_t smb = smaddr(sm);

    // ldmatrix lane mapping
    const int a_r = lane & 15, a_k = (lane >> 4) << 3;
    const int b_r = (lane & 7) + ((lane >> 4) << 3);
    const int b_k = ((lane >> 3) & 1) << 3;

    float acc[4][4][4];
    #pragma unroll
    for (int i = 0; i < 4; i++)
        #pragma unroll
        for (int j = 0; j < 4; j++)
            #pragma unroll
            for (int k = 0; k < 4; k++) acc[i][j][k] = 0.f;

    #define ISSUE(kt, s) do {                                                  \
        int _k = (kt) << 5;                                                     \
        uint32_t _sb = smb + (uint32_t)(s) * STAGE_B;                           \
        _Pragma("unroll")                                                       \
        for (int _i = 0; _i < 2; _i++) {                                        \
            int _r = r0 + 64 * _i;                                              \
            uint32_t _d = _sb + (uint32_t)(_r * SP + c0) * 2;                   \
            CPA(_d,                  Ah + (size_t)(bm + _r) * K + _k + c0);     \
            CPA(_d + STG_ELEM*2,     Al + (size_t)(bm + _r) * K + _k + c0);     \
            CPA(_d + 2*STG_ELEM*2,   Bh + (size_t)(bn + _r) * K + _k + c0);     \
            CPA(_d + 3*STG_ELEM*2,   Bl + (size_t)(bn + _r) * K + _k + c0);     \
        }                                                                       \
        CPCOMMIT();                                                             \
    } while (0)

    ISSUE(0, 0);
    ISSUE(1, 1);

    for (int kt = 0; kt < nIter; kt++) {
        CPWAIT1();
        __syncthreads();
        const int s = kt % 3;
        const uint32_t sb = smb + (uint32_t)s * STAGE_B;

        #pragma unroll
        for (int sub = 0; sub < 32; sub += 16) {
            unsigned ah[4][4], al[4][4], bh[2][4], bl[2][4];
            #pragma unroll
            for (int mt = 0; mt < 4; mt++) {
                uint32_t aa = sb + (uint32_t)((wm + mt*16 + a_r) * SP + sub + a_k) * 2;
                LDSM4(ah[mt][0], ah[mt][1], ah[mt][2], ah[mt][3], aa);
                LDSM4(al[mt][0], al[mt][1], al[mt][2], al[mt][3], aa + STG_ELEM*2);
            }
            #pragma unroll
            for (int p = 0; p < 2; p++) {
                uint32_t ba = sb + 2*STG_ELEM*2 +
                              (uint32_t)((wn + p*16 + b_r) * SP + sub + b_k) * 2;
                LDSM4(bh[p][0], bh[p][1], bh[p][2], bh[p][3], ba);
                LDSM4(bl[p][0], bl[p][1], bl[p][2], bl[p][3], ba + STG_ELEM*2);
            }
            #pragma unroll
            for (int mt = 0; mt < 4; mt++)
                #pragma unroll
                for (int nt = 0; nt < 4; nt++) {
                    unsigned h0 = bh[nt>>1][(nt&1)*2], h1 = bh[nt>>1][(nt&1)*2+1];
                    unsigned l0 = bl[nt>>1][(nt&1)*2], l1 = bl[nt>>1][(nt&1)*2+1];
                    MMA(acc[mt][nt], ah[mt], h0, h1);
                    MMA(acc[mt][nt], ah[mt], l0, l1);
                    MMA(acc[mt][nt], al[mt], h0, h1);
                }
        }

        int nk = kt + 2;
        if (nk < nIter) { ISSUE(nk, nk % 3); }
        else            { CPCOMMIT(); }
    }

    // epilogue
    const int g = lane >> 2, q = lane & 3;
    #pragma unroll
    for (int mt = 0; mt < 4; mt++) {
        int row0 = bm + wm + mt * 16 + g;
        #pragma unroll
        for (int nt = 0; nt < 4; nt++) {
            int col = bn + wn + nt * 8 + 2 * q;
            if (col < N) {
                float2 v0, v1;
                v0.x = acc[mt][nt][0]; v0.y = acc[mt][nt][1];
                v1.x = acc[mt][nt][2]; v1.y = acc[mt][nt][3];
                if (R) {
                    const float* rr0 = R + (size_t)row0 * N + col;
                    const float* rr1 = R + (size_t)(row0 + 8) * N + col;
                    v0.x += rr0[0]; v0.y += rr0[1];
                    v1.x += rr1[0]; v1.y += rr1[1];
                }
                *(float2*)(C + (size_t)row0 * N + col) = v0;
                *(float2*)(C + (size_t)(row0 + 8) * N + col) = v1;
            }
        }
    }
    #undef ISSUE
}

// ---------------- dt = softplus(raw + bias), dA = exp(dt * -exp(A_log)) -----
__global__ void k_dtda(const float* __restrict__ dtb, const float* __restrict__ alog) {
    int i = blockIdx.x * 256 + threadIdx.x;
    if (i >= TT * NH) return;
    int h = i % NH, t = i / NH;
    float xv = g_zx[(size_t)t * DP + (DI + CD) + h] + dtb[h];
    float dt = (xv > 20.f) ? xv : log1pf(expf(xv));
    float A = -expf(alog[h]);
    g_dt[i] = dt;
    g_dA[i] = expf(dt * A);
}

// ---------------- causal depthwise conv(4) + bias + SiLU --------------------
__global__ void k_conv(const float* __restrict__ cw, const float* __restrict__ cb) {
    int i = blockIdx.x * 256 + threadIdx.x;
    if (i >= TT * CD) return;
    int c = i % CD, t = i / CD, b = t / LEN, l = t % LEN;
    float acc = cb[c];
    #pragma unroll
    for (int k = 0; k < 4; k++) {
        int ll = l - 3 + k;
        if (ll >= 0)
            acc += g_zx[((size_t)(b * LEN + ll)) * DP + DI + c] * cw[c * 4 + k];
    }
    g_xbc[(size_t)t * CD + c] = acc / (1.f + expf(-acc));
}

// ---------------- scan phase 1: per-chunk local final state + decay product -
__global__ void k_scan1() {
    int c = blockIdx.x, hd = blockIdx.y, b = blockIdx.z;
    int tid = threadIdx.x;
    __shared__ float sx[CH * HD];
    __shared__ float sB[CH * DS];
    __shared__ float sdt[CH];
    __shared__ float sdA[CH];
    int t0 = c * CH;
    size_t rb = ((size_t)(b * LEN + t0)) * CD;
    for (int idx = tid; idx < CH * HD; idx += 256) {
        int t = idx >> 6, p = idx & 63;
        sx[idx] = g_xbc[rb + (size_t)t * CD + hd * HD + p];
    }
    for (int idx = tid; idx < CH * DS; idx += 256) {
        int t = idx >> 4, n = idx & 15;
        sB[idx] = g_xbc[rb + (size_t)t * CD + DI + n];
    }
    for (int idx = tid; idx < CH; idx += 256) {
        int tg = (b * LEN + t0 + idx) * NH + hd;
        sdt[idx] = g_dt[tg];
        sdA[idx] = g_dA[tg];
    }
    __syncthreads();
    int n = tid & 15, pg = tid >> 4;
    float h0 = 0.f, h1 = 0.f, h2 = 0.f, h3 = 0.f, run = 1.f;
    for (int t = 0; t < CH; t++) {
        float dA = sdA[t];
        float coef = sdt[t] * sB[t * DS + n];
        run *= dA;
        h0 = dA * h0 + coef * sx[t * HD + pg];
        h1 = dA * h1 + coef * sx[t * HD + pg + 16];
        h2 = dA * h2 + coef * sx[t * HD + pg + 32];
        h3 = dA * h3 + coef * sx[t * HD + pg + 48];
    }
    size_t base = ((size_t)((b * NH + hd) * NC + c)) * (HD * DS);
    g_hl[base + (pg)      * DS + n] = h0;
    g_hl[base + (pg + 16) * DS + n] = h1;
    g_hl[base + (pg + 32) * DS + n] = h2;
    g_hl[base + (pg + 48) * DS + n] = h3;
    if (tid == 0) g_P[(b * NH + hd) * NC + c] = run;
}

// ---------------- scan phase 2: inter-chunk combine (48 blocks, sequential) -
__global__ void k_scan2() {
    int bh = blockIdx.x, tid = threadIdx.x;
    float H0 = 0.f, H1 = 0.f, H2 = 0.f, H3 = 0.f;
    for (int c = 0; c < NC; c++) {
        size_t base = ((size_t)(bh * NC + c)) * (HD * DS);
        float P = g_P[bh * NC + c];
        g_hs[base + tid]       = H0;
        g_hs[base + tid + 256] = H1;
        g_hs[base + tid + 512] = H2;
        g_hs[base + tid + 768] = H3;
        H0 = P * H0 + g_hl[base + tid];
        H1 = P * H1 + g_hl[base + tid + 256];
        H2 = P * H2 + g_hl[base + tid + 512];
        H3 = P * H3 + g_hl[base + tid + 768];
    }
}

// ---------------- scan phase 3: full scan w/ correct init, emit y -----------
__global__ void k_scan3(const float* __restrict__ Dp) {
    int c = blockIdx.x, hd = blockIdx.y, b = blockIdx.z;
    int tid = threadIdx.x;
    __shared__ float sx[CH * HD];
    __shared__ float sB[CH * DS];
    __shared__ float sC[CH * DS];
    __shared__ float sdt[CH];
    __shared__ float sdA[CH];
    int t0 = c * CH;
    size_t rb = ((size_t)(b * LEN + t0)) * CD;
    for (int idx = tid; idx < CH * HD; idx += 256) {
        int t = idx >> 6, p = idx & 63;
        sx[idx] = g_xbc[rb + (size_t)t * CD + hd * HD + p];
    }
    for (int idx = tid; idx < CH * DS; idx += 256) {
        int t = idx >> 4, n = idx & 15;
        sB[idx] = g_xbc[rb + (size_t)t * CD + DI + n];
        sC[idx] = g_xbc[rb + (size_t)t * CD + DI + DS + n];
    }
    for (int idx = tid; idx < CH; idx += 256) {
        int tg = (b * LEN + t0 + idx) * NH + hd;
        sdt[idx] = g_dt[tg];
        sdA[idx] = g_dA[tg];
    }
    __syncthreads();
    int n = tid & 15, pg = tid >> 4;
    size_t base = ((size_t)((b * NH + hd) * NC + c)) * (HD * DS);
    float h0 = g_hs[base + (pg)      * DS + n];
    float h1 = g_hs[base + (pg + 16) * DS + n];
    float h2 = g_hs[base + (pg + 32) * DS + n];
    float h3 = g_hs[base + (pg + 48) * DS + n];
    float Dh = Dp[hd];
    for (int t = 0; t < CH; t++) {
        float dA = sdA[t];
        float coef = sdt[t] * sB[t * DS + n];
        float x0 = sx[t * HD + pg];
        float x1 = sx[t * HD + pg + 16];
        float x2 = sx[t * HD + pg + 32];
        float x3 = sx[t * HD + pg + 48];
        h0 = dA * h0 + coef * x0;
        h1 = dA * h1 + coef * x1;
        h2 = dA * h2 + coef * x2;
        h3 = dA * h3 + coef * x3;
        float Ct = sC[t * DS + n];
        float y0 = h0 * Ct, y1 = h1 * Ct, y2 = h2 * Ct, y3 = h3 * Ct;
        #pragma unroll
        for (int m = 1; m < 16; m <<= 1) {
            y0 += __shfl_xor_sync(0xffffffffu, y0, m);
            y1 += __shfl_xor_sync(0xffffffffu, y1, m);
            y2 += __shfl_xor_sync(0xffffffffu, y2, m);
            y3 += __shfl_xor_sync(0xffffffffu, y3, m);
        }
        if (n == 0) {
            float* yr = g_y + ((size_t)(b * LEN + t0 + t)) * DI + hd * HD;
            yr[pg]      = y0 + Dh * x0;
            yr[pg + 16] = y1 + Dh * x1;
            yr[pg + 32] = y2 + Dh * x2;
            yr[pg + 48] = y3 + Dh * x3;
        }
    }
}

// ---------------- gating + RMSNorm -> bf16 hi/lo ----------------------------
__global__ void k_gate(const float* __restrict__ gnw) {
    int row = blockIdx.x, tid = threadIdx.x;
    const float* yr = g_y  + (size_t)row * DI;
    const float* zr = g_zx + (size_t)row * DP;  // z = first DI columns
    float gv[6];
    float sq = 0.f;
    #pragma unroll
    for (int i = 0; i < 6; i++) {
        int cc = tid + 256 * i;
        float z = zr[cc];
        float g = yr[cc] * (z / (1.f + expf(-z)));
        gv[i] = g;
        sq += g * g;
    }
    __shared__ float sh[8];
    #pragma unroll
    for (int m = 16; m; m >>= 1) sq += __shfl_xor_sync(0xffffffffu, sq, m);
    if ((tid & 31) == 0) sh[tid >> 5] = sq;
    __syncthreads();
    if (tid < 32) {
        float a = (tid < 8) ? sh[tid] : 0.f;
        #pragma unroll
        for (int m = 4; m; m >>= 1) a += __shfl_xor_sync(0xffffffffu, a, m);
        if (tid == 0) sh[0] = a;
    }
    __syncthreads();
    float inv = rsqrtf(sh[0] * (1.f / DI) + 1e-5f);
    size_t base = (size_t)row * DI;
    #pragma unroll
    for (int i = 0; i < 6; i++) {
        int cc = tid + 256 * i;
        split1(gv[i] * inv * gnw[cc], g_gh + base + cc, g_gl + base + cc);
    }
}

// ---------------- launcher ---------------------------------------------------
extern "C" void kernel_launch(void* const* d_in, const int* in_sizes, int n_in,
                              void* d_out, int out_size) {
    const float* x       = (const float*)d_in[0];
    const float* ln_w    = (const float*)d_in[1];
    const float* ln_b    = (const float*)d_in[2];
    const float* W_in    = (const float*)d_in[3];
    const float* conv_w  = (const float*)d_in[4];
    const float* conv_b  = (const float*)d_in[5];
    const float* dt_bias = (const float*)d_in[6];
    const float* A_log   = (const float*)d_in[7];
    const float* Dv      = (const float*)d_in[8];
    const float* gnw     = (const float*)d_in[9];
    const float* W_out   = (const float*)d_in[10];
    float* out = (float*)d_out;

    __nv_bfloat16 *puh, *pul, *pw1h, *pw1l, *pgh, *pgl, *pw2h, *pw2l;
    float *pzx;
    cudaGetSymbolAddress((void**)&pzx,  g_zx);
    cudaGetSymbolAddress((void**)&puh,  g_uh);
    cudaGetSymbolAddress((void**)&pul,  g_ul);
    cudaGetSymbolAddress((void**)&pw1h, g_W1h);
    cudaGetSymbolAddress((void**)&pw1l, g_W1l);
    cudaGetSymbolAddress((void**)&pgh,  g_gh);
    cudaGetSymbolAddress((void**)&pgl,  g_gl);
    cudaGetSymbolAddress((void**)&pw2h, g_W2h);
    cudaGetSymbolAddress((void**)&pw2l, g_W2l);

    cudaFuncSetAttribute(k_gemm_bf, cudaFuncAttributeMaxDynamicSharedMemorySize,
                         3 * STAGE_B);

    k_split<<<(NP1*DM + 255)/256, 256>>>(W_in,  pw1h, pw1l, DP*DM, NP1*DM);
    k_split<<<(DM*DI + 255)/256, 256>>>(W_out, pw2h, pw2l, DM*DI, DM*DI);
    k_ln<<<TT, 256>>>(x, ln_w, ln_b);
    k_gemm_bf<<<dim3(NP1/128, TT/128), 256, 3*STAGE_B>>>(
        puh, pul, pw1h, pw1l, pzx, nullptr, TT, DP, DM);
    k_dtda<<<(TT * NH + 255) / 256, 256>>>(dt_bias, A_log);
    k_conv<<<(TT * CD + 255) / 256, 256>>>(conv_w, conv_b);
    k_scan1<<<dim3(NC, NH, BSZ), 256>>>();
    k_scan2<<<BSZ * NH, 256>>>();
    k_scan3<<<dim3(NC, NH, BSZ), 256>>>(Dv);
    k_gate<<<TT, 256>>>(gnw);
    k_gemm_bf<<<dim3(DM/128, TT/128), 256, 3*STAGE_B>>>(
        pgh, pgl, pw2h, pw2l, out, x, TT, DM, DI);
}

// round 5
// speedup vs baseline: 2.3445x; 1.0708x over previous
#include <cuda_runtime.h>
#include <cuda_bf16.h>
#include <math.h>
#include <stdint.h>

#define BSZ 2
#define LEN 4096
#define TT (BSZ*LEN)          // 8192 tokens
#define DM 768
#define DI 1536
#define DS 16
#define NH 24
#define HD 64
#define CD 1568               // DI + 2*DS
#define DP 3128               // 2*DI + 2*DS + NH
#define NP1 3328              // DP padded to 256
#define NC 64                 // chunks
#define CH 64                 // chunk length (LEN/NC)

// ---------------- scratch (static device arrays; no runtime alloc) ----------
__device__ __align__(16) float g_zx[(size_t)TT*DP];
__device__ __align__(16) float g_xbc[(size_t)TT*CD];
__device__ float g_dt[TT*NH];
__device__ float g_dA[TT*NH];
__device__ __align__(16) float g_y[(size_t)TT*DI];
__device__ __align__(16) float g_hl[BSZ*NH*NC*HD*DS];
__device__ __align__(16) float g_hs[BSZ*NH*NC*HD*DS];
__device__ float g_P[BSZ*NH*NC];
// bf16 hi/lo operand buffers (16B aligned for cp.async)
__device__ __align__(16) __nv_bfloat16 g_uh[(size_t)TT*DM];
__device__ __align__(16) __nv_bfloat16 g_ul[(size_t)TT*DM];
__device__ __align__(16) __nv_bfloat16 g_W1h[(size_t)NP1*DM];
__device__ __align__(16) __nv_bfloat16 g_W1l[(size_t)NP1*DM];
__device__ __align__(16) __nv_bfloat16 g_gh[(size_t)TT*DI];
__device__ __align__(16) __nv_bfloat16 g_gl[(size_t)TT*DI];
__device__ __align__(16) __nv_bfloat16 g_W2h[(size_t)DM*DI];
__device__ __align__(16) __nv_bfloat16 g_W2l[(size_t)DM*DI];

__device__ __forceinline__ void split1(float v, __nv_bfloat16* ph, __nv_bfloat16* pl) {
    __nv_bfloat16 h = __float2bfloat16_rn(v);
    *ph = h;
    *pl = __float2bfloat16_rn(v - __bfloat162float(h));
}

// ---------------- weight split ----------------------------------------------
__global__ void k_split(const float* __restrict__ W, __nv_bfloat16* __restrict__ H,
                        __nv_bfloat16* __restrict__ L, int n, int nPad) {
    int i = blockIdx.x * 256 + threadIdx.x;
    if (i >= nPad) return;
    float v = (i < n) ? W[i] : 0.f;
    split1(v, H + i, L + i);
}

// ---------------- layernorm -> bf16 hi/lo ------------------------------------
__global__ void k_ln(const float* __restrict__ x, const float* __restrict__ w,
                     const float* __restrict__ bb) {
    int row = blockIdx.x;
    int tid = threadIdx.x;
    const float* xr = x + (size_t)row * DM;
    float v0 = xr[tid], v1 = xr[tid + 256], v2 = xr[tid + 512];
    float s  = v0 + v1 + v2;
    float sq = v0*v0 + v1*v1 + v2*v2;
    __shared__ float sh[16];
    #pragma unroll
    for (int m = 16; m; m >>= 1) {
        s  += __shfl_xor_sync(0xffffffffu, s,  m);
        sq += __shfl_xor_sync(0xffffffffu, sq, m);
    }
    if ((tid & 31) == 0) { sh[tid >> 5] = s; sh[8 + (tid >> 5)] = sq; }
    __syncthreads();
    if (tid < 32) {
        float a  = (tid < 8) ? sh[tid]     : 0.f;
        float b2 = (tid < 8) ? sh[8 + tid] : 0.f;
        #pragma unroll
        for (int m = 4; m; m >>= 1) {
            a  += __shfl_xor_sync(0xffffffffu, a,  m);
            b2 += __shfl_xor_sync(0xffffffffu, b2, m);
        }
        if (tid == 0) { sh[0] = a; sh[8] = b2; }
    }
    __syncthreads();
    float mu  = sh[0] * (1.f / DM);
    float var = sh[8] * (1.f / DM) - mu * mu;
    float inv = rsqrtf(var + 1e-5f);
    size_t base = (size_t)row * DM;
    float u0 = (v0 - mu) * inv * w[tid]       + bb[tid];
    float u1 = (v1 - mu) * inv * w[tid + 256] + bb[tid + 256];
    float u2 = (v2 - mu) * inv * w[tid + 512] + bb[tid + 512];
    split1(u0, g_uh + base + tid,       g_ul + base + tid);
    split1(u1, g_uh + base + tid + 256, g_ul + base + tid + 256);
    split1(u2, g_uh + base + tid + 512, g_ul + base + tid + 512);
}

// ============================================================================
// HMMA NT GEMM, pre-split bf16 hi/lo, 3-pass. CTA tile 128x256, warp 64x64.
// 3-stage cp.async, ldmatrix.x4. M%128==0, K%32==0, B padded to grid N.
// ============================================================================
#define SP 40                   // smem row pitch in bf16 (32 data + 8 pad)
#define A_ELE (128*SP)          // 5120
#define B_ELE (256*SP)          // 10240
#define OFF_AH 0
#define OFF_AL (A_ELE*2)
#define OFF_BH (2*A_ELE*2)
#define OFF_BL (2*A_ELE*2 + B_ELE*2)
#define STAGE_B (2*A_ELE*2 + 2*B_ELE*2)   // 61440 bytes
#define GSMEM (3*STAGE_B)

__device__ __forceinline__ uint32_t smaddr(const void* p) {
    return (uint32_t)__cvta_generic_to_shared(p);
}
#define CPA(d, s) asm volatile("cp.async.cg.shared.global [%0], [%1], 16;\n" :: "r"(d), "l"(s))
#define CPCOMMIT() asm volatile("cp.async.commit_group;\n")
#define CPWAIT1() asm volatile("cp.async.wait_group 1;\n")
#define LDSM4(r0,r1,r2,r3,a) asm volatile( \
    "ldmatrix.sync.aligned.m8n8.x4.shared.b16 {%0,%1,%2,%3}, [%4];\n" \
    : "=r"(r0),"=r"(r1),"=r"(r2),"=r"(r3) : "r"(a))
#define MMA(d, a, b0, b1) \
  asm volatile("mma.sync.aligned.m16n8k16.row.col.f32.bf16.bf16.f32 " \
      "{%0,%1,%2,%3}, {%4,%5,%6,%7}, {%8,%9}, {%0,%1,%2,%3};\n" \
      : "+f"(d[0]), "+f"(d[1]), "+f"(d[2]), "+f"(d[3]) \
      : "r"(a[0]), "r"(a[1]), "r"(a[2]), "r"(a[3]), "r"(b0), "r"(b1))

__global__ void __launch_bounds__(256, 1)
k_gemm_bf(const __nv_bfloat16* __restrict__ Ah, const __nv_bfloat16* __restrict__ Al,
          const __nv_bfloat16* __restrict__ Bh, const __nv_bfloat16* __restrict__ Bl,
          float* __restrict__ C, const float* __restrict__ R,
          int M, int N, int K) {
    extern __shared__ __nv_bfloat16 sm[];
    const int tid = threadIdx.x;
    const int warp = tid >> 5, lane = tid & 31;
    const int wm = (warp & 1) * 64;
    const int wn = (warp >> 1) * 64;
    const int bm = blockIdx.y * 128, bn = blockIdx.x * 256;
    const int nIter = K >> 5;

    const int r0 = tid >> 2;             // 0..63
    const int c0 = (tid & 3) << 3;       // 0,8,16,24
    const uint32_t smb = smaddr(sm);

    const int a_r = lane & 15, a_k = (lane >> 4) << 3;
    const int b_r = (lane & 7) + ((lane >> 4) << 3);
    const int b_k = ((lane >> 3) & 1) << 3;

    float acc[4][8][4];
    #pragma unroll
    for (int i = 0; i < 4; i++)
        #pragma unroll
        for (int j = 0; j < 8; j++)
            #pragma unroll
            for (int k = 0; k < 4; k++) acc[i][j][k] = 0.f;

    #define ISSUE(kt) do {                                                     \
        int _b = (kt) % 3, _k = (kt) << 5;                                     \
        uint32_t _sb = smb + (uint32_t)_b * STAGE_B;                           \
        _Pragma("unroll")                                                      \
        for (int _i = 0; _i < 2; _i++) {                                       \
            int _r = r0 + 64 * _i;                                             \
            uint32_t _d = (uint32_t)(_r * SP + c0) * 2;                        \
            size_t _g = (size_t)(bm + _r) * K + _k + c0;                       \
            CPA(_sb + OFF_AH + _d, Ah + _g);                                   \
            CPA(_sb + OFF_AL + _d, Al + _g);                                   \
        }                                                                      \
        _Pragma("unroll")                                                      \
        for (int _i = 0; _i < 4; _i++) {                                       \
            int _r = r0 + 64 * _i;                                             \
            uint32_t _d = (uint32_t)(_r * SP + c0) * 2;                        \
            size_t _g = (size_t)(bn + _r) * K + _k + c0;                       \
            CPA(_sb + OFF_BH + _d, Bh + _g);                                   \
            CPA(_sb + OFF_BL + _d, Bl + _g);                                   \
        }                                                                      \
        CPCOMMIT();                                                            \
    } while (0)

    ISSUE(0);
    ISSUE(1);

    for (int kt = 0; kt < nIter; kt++) {
        CPWAIT1();
        __syncthreads();
        const int s = kt % 3;
        const uint32_t sb = smb + (uint32_t)s * STAGE_B;

        #pragma unroll
        for (int sub = 0; sub < 32; sub += 16) {
            unsigned ah[4][4], al[4][4];
            #pragma unroll
            for (int mt = 0; mt < 4; mt++) {
                uint32_t aa = sb + (uint32_t)((wm + mt*16 + a_r) * SP + sub + a_k) * 2;
                LDSM4(ah[mt][0], ah[mt][1], ah[mt][2], ah[mt][3], aa + OFF_AH);
                LDSM4(al[mt][0], al[mt][1], al[mt][2], al[mt][3], aa + OFF_AL);
            }
            #pragma unroll
            for (int p = 0; p < 4; p++) {
                unsigned bh[4], bl[4];
                uint32_t ba = sb + (uint32_t)((wn + p*16 + b_r) * SP + sub + b_k) * 2;
                LDSM4(bh[0], bh[1], bh[2], bh[3], ba + OFF_BH);
                LDSM4(bl[0], bl[1], bl[2], bl[3], ba + OFF_BL);
                #pragma unroll
                for (int mt = 0; mt < 4; mt++) {
                    MMA(acc[mt][2*p],   ah[mt], bh[0], bh[1]);
                    MMA(acc[mt][2*p],   ah[mt], bl[0], bl[1]);
                    MMA(acc[mt][2*p],   al[mt], bh[0], bh[1]);
                    MMA(acc[mt][2*p+1], ah[mt], bh[2], bh[3]);
                    MMA(acc[mt][2*p+1], ah[mt], bl[2], bl[3]);
                    MMA(acc[mt][2*p+1], al[mt], bh[2], bh[3]);
                }
            }
        }

        int nk = kt + 2;
        if (nk < nIter) { ISSUE(nk); }
        else            { CPCOMMIT(); }
    }

    // epilogue
    const int g = lane >> 2, q = lane & 3;
    #pragma unroll
    for (int mt = 0; mt < 4; mt++) {
        int row0 = bm + wm + mt * 16 + g;
        #pragma unroll
        for (int nt = 0; nt < 8; nt++) {
            int col = bn + wn + nt * 8 + 2 * q;
            if (col < N) {
                float2 v0, v1;
                v0.x = acc[mt][nt][0]; v0.y = acc[mt][nt][1];
                v1.x = acc[mt][nt][2]; v1.y = acc[mt][nt][3];
                if (R) {
                    const float* rr0 = R + (size_t)row0 * N + col;
                    const float* rr1 = R + (size_t)(row0 + 8) * N + col;
                    v0.x += rr0[0]; v0.y += rr0[1];
                    v1.x += rr1[0]; v1.y += rr1[1];
                }
                *(float2*)(C + (size_t)row0 * N + col) = v0;
                *(float2*)(C + (size_t)(row0 + 8) * N + col) = v1;
            }
        }
    }
    #undef ISSUE
}

// ---------------- dt = softplus(raw + bias), dA = exp(dt * -exp(A_log)) -----
__global__ void k_dtda(const float* __restrict__ dtb, const float* __restrict__ alog) {
    int i = blockIdx.x * 256 + threadIdx.x;
    if (i >= TT * NH) return;
    int h = i % NH, t = i / NH;
    float xv = g_zx[(size_t)t * DP + (DI + CD) + h] + dtb[h];
    float dt = (xv > 20.f) ? xv : log1pf(expf(xv));
    float A = -expf(alog[h]);
    g_dt[i] = dt;
    g_dA[i] = expf(dt * A);
}

// ---------------- causal depthwise conv(4) + bias + SiLU --------------------
__global__ void k_conv(const float* __restrict__ cw, const float* __restrict__ cb) {
    int i = blockIdx.x * 256 + threadIdx.x;
    if (i >= TT * CD) return;
    int c = i % CD, t = i / CD, b = t / LEN, l = t % LEN;
    float acc = cb[c];
    #pragma unroll
    for (int k = 0; k < 4; k++) {
        int ll = l - 3 + k;
        if (ll >= 0)
            acc += g_zx[((size_t)(b * LEN + ll)) * DP + DI + c] * cw[c * 4 + k];
    }
    g_xbc[(size_t)t * CD + c] = acc / (1.f + expf(-acc));
}

// ---------------- scan phase 1: thread-per-p, h[16] in registers ------------
__global__ void __launch_bounds__(64)
k_scan1() {
    int c = blockIdx.x, hd = blockIdx.y, b = blockIdx.z;
    int p = threadIdx.x;
    __shared__ float sx[CH * HD];
    __shared__ __align__(16) float sB[CH * DS];
    __shared__ float sdt[CH];
    __shared__ float sdA[CH];
    int t0 = c * CH;
    size_t rb = ((size_t)(b * LEN + t0)) * CD;
    for (int idx = p; idx < CH * HD; idx += 64) {
        int t = idx >> 6, pp = idx & 63;
        sx[idx] = g_xbc[rb + (size_t)t * CD + hd * HD + pp];
    }
    for (int idx = p; idx < CH * DS; idx += 64) {
        int t = idx >> 4, n = idx & 15;
        sB[idx] = g_xbc[rb + (size_t)t * CD + DI + n];
    }
    {
        int tg = (b * LEN + t0 + p) * NH + hd;
        sdt[p] = g_dt[tg];
        sdA[p] = g_dA[tg];
    }
    __syncthreads();
    float h[16];
    #pragma unroll
    for (int n = 0; n < 16; n++) h[n] = 0.f;
    float run = 1.f;
    for (int t = 0; t < CH; t++) {
        float dA = sdA[t];
        float s = sdt[t] * sx[t * HD + p];
        run *= dA;
        #pragma unroll
        for (int n = 0; n < 16; n += 4) {
            float4 Bv = *(const float4*)&sB[t * DS + n];
            h[n]   = fmaf(dA, h[n],   s * Bv.x);
            h[n+1] = fmaf(dA, h[n+1], s * Bv.y);
            h[n+2] = fmaf(dA, h[n+2], s * Bv.z);
            h[n+3] = fmaf(dA, h[n+3], s * Bv.w);
        }
    }
    size_t base = ((size_t)((b * NH + hd) * NC + c)) * (HD * DS);
    #pragma unroll
    for (int n = 0; n < 16; n += 4)
        *(float4*)&g_hl[base + p * DS + n] = make_float4(h[n], h[n+1], h[n+2], h[n+3]);
    if (p == 0) g_P[(b * NH + hd) * NC + c] = run;
}

// ---------------- scan phase 2: inter-chunk combine (48 blocks, sequential) -
__global__ void k_scan2() {
    int bh = blockIdx.x, tid = threadIdx.x;
    float H0 = 0.f, H1 = 0.f, H2 = 0.f, H3 = 0.f;
    for (int c = 0; c < NC; c++) {
        size_t base = ((size_t)(bh * NC + c)) * (HD * DS);
        float P = g_P[bh * NC + c];
        g_hs[base + tid]       = H0;
        g_hs[base + tid + 256] = H1;
        g_hs[base + tid + 512] = H2;
        g_hs[base + tid + 768] = H3;
        H0 = P * H0 + g_hl[base + tid];
        H1 = P * H1 + g_hl[base + tid + 256];
        H2 = P * H2 + g_hl[base + tid + 512];
        H3 = P * H3 + g_hl[base + tid + 768];
    }
}

// ---------------- scan phase 3: thread-per-p, emits y ------------------------
__global__ void __launch_bounds__(64)
k_scan3(const float* __restrict__ Dp) {
    int c = blockIdx.x, hd = blockIdx.y, b = blockIdx.z;
    int p = threadIdx.x;
    __shared__ float sx[CH * HD];
    __shared__ __align__(16) float sB[CH * DS];
    __shared__ __align__(16) float sC[CH * DS];
    __shared__ float sdt[CH];
    __shared__ float sdA[CH];
    int t0 = c * CH;
    size_t rb = ((size_t)(b * LEN + t0)) * CD;
    for (int idx = p; idx < CH * HD; idx += 64) {
        int t = idx >> 6, pp = idx & 63;
        sx[idx] = g_xbc[rb + (size_t)t * CD + hd * HD + pp];
    }
    for (int idx = p; idx < CH * DS; idx += 64) {
        int t = idx >> 4, n = idx & 15;
        sB[idx] = g_xbc[rb + (size_t)t * CD + DI + n];
        sC[idx] = g_xbc[rb + (size_t)t * CD + DI + DS + n];
    }
    {
        int tg = (b * LEN + t0 + p) * NH + hd;
        sdt[p] = g_dt[tg];
        sdA[p] = g_dA[tg];
    }
    __syncthreads();
    size_t base = ((size_t)((b * NH + hd) * NC + c)) * (HD * DS);
    float h[16];
    #pragma unroll
    for (int n = 0; n < 16; n += 4) {
        float4 v = *(const float4*)&g_hs[base + p * DS + n];
        h[n] = v.x; h[n+1] = v.y; h[n+2] = v.z; h[n+3] = v.w;
    }
    float Dh = Dp[hd];
    for (int t = 0; t < CH; t++) {
        float dA = sdA[t];
        float xv = sx[t * HD + p];
        float s = sdt[t] * xv;
        float y = 0.f;
        #pragma unroll
        for (int n = 0; n < 16; n += 4) {
            float4 Bv = *(const float4*)&sB[t * DS + n];
            float4 Cv = *(const float4*)&sC[t * DS + n];
            h[n]   = fmaf(dA, h[n],   s * Bv.x);
            h[n+1] = fmaf(dA, h[n+1], s * Bv.y);
            h[n+2] = fmaf(dA, h[n+2], s * Bv.z);
            h[n+3] = fmaf(dA, h[n+3], s * Bv.w);
            y += h[n]*Cv.x + h[n+1]*Cv.y + h[n+2]*Cv.z + h[n+3]*Cv.w;
        }
        g_y[((size_t)(b * LEN + t0 + t)) * DI + hd * HD + p] = y + Dh * xv;
    }
}

// ---------------- gating + RMSNorm -> bf16 hi/lo ----------------------------
__global__ void k_gate(const float* __restrict__ gnw) {
    int row = blockIdx.x, tid = threadIdx.x;
    const float* yr = g_y  + (size_t)row * DI;
    const float* zr = g_zx + (size_t)row * DP;
    float gv[6];
    float sq = 0.f;
    #pragma unroll
    for (int i = 0; i < 6; i++) {
        int cc = tid + 256 * i;
        float z = zr[cc];
        float g = yr[cc] * (z / (1.f + expf(-z)));
        gv[i] = g;
        sq += g * g;
    }
    __shared__ float sh[8];
    #pragma unroll
    for (int m = 16; m; m >>= 1) sq += __shfl_xor_sync(0xffffffffu, sq, m);
    if ((tid & 31) == 0) sh[tid >> 5] = sq;
    __syncthreads();
    if (tid < 32) {
        float a = (tid < 8) ? sh[tid] : 0.f;
        #pragma unroll
        for (int m = 4; m; m >>= 1) a += __shfl_xor_sync(0xffffffffu, a, m);
        if (tid == 0) sh[0] = a;
    }
    __syncthreads();
    float inv = rsqrtf(sh[0] * (1.f / DI) + 1e-5f);
    size_t base = (size_t)row * DI;
    #pragma unroll
    for (int i = 0; i < 6; i++) {
        int cc = tid + 256 * i;
        split1(gv[i] * inv * gnw[cc], g_gh + base + cc, g_gl + base + cc);
    }
}

// ---------------- launcher ---------------------------------------------------
extern "C" void kernel_launch(void* const* d_in, const int* in_sizes, int n_in,
                              void* d_out, int out_size) {
    const float* x       = (const float*)d_in[0];
    const float* ln_w    = (const float*)d_in[1];
    const float* ln_b    = (const float*)d_in[2];
    const float* W_in    = (const float*)d_in[3];
    const float* conv_w  = (const float*)d_in[4];
    const float* conv_b  = (const float*)d_in[5];
    const float* dt_bias = (const float*)d_in[6];
    const float* A_log   = (const float*)d_in[7];
    const float* Dv      = (const float*)d_in[8];
    const float* gnw     = (const float*)d_in[9];
    const float* W_out   = (const float*)d_in[10];
    float* out = (float*)d_out;

    __nv_bfloat16 *puh, *pul, *pw1h, *pw1l, *pgh, *pgl, *pw2h, *pw2l;
    float *pzx;
    cudaGetSymbolAddress((void**)&pzx,  g_zx);
    cudaGetSymbolAddress((void**)&puh,  g_uh);
    cudaGetSymbolAddress((void**)&pul,  g_ul);
    cudaGetSymbolAddress((void**)&pw1h, g_W1h);
    cudaGetSymbolAddress((void**)&pw1l, g_W1l);
    cudaGetSymbolAddress((void**)&pgh,  g_gh);
    cudaGetSymbolAddress((void**)&pgl,  g_gl);
    cudaGetSymbolAddress((void**)&pw2h, g_W2h);
    cudaGetSymbolAddress((void**)&pw2l, g_W2l);

    cudaFuncSetAttribute(k_gemm_bf, cudaFuncAttributeMaxDynamicSharedMemorySize, GSMEM);

    k_split<<<(NP1*DM + 255)/256, 256>>>(W_in,  pw1h, pw1l, DP*DM, NP1*DM);
    k_split<<<(DM*DI + 255)/256, 256>>>(W_out, pw2h, pw2l, DM*DI, DM*DI);
    k_ln<<<TT, 256>>>(x, ln_w, ln_b);
    k_gemm_bf<<<dim3(NP1/256, TT/128), 256, GSMEM>>>(
        puh, pul, pw1h, pw1l, pzx, nullptr, TT, DP, DM);
    k_dtda<<<(TT * NH + 255) / 256, 256>>>(dt_bias, A_log);
    k_conv<<<(TT * CD + 255) / 256, 256>>>(conv_w, conv_b);
    k_scan1<<<dim3(NC, NH, BSZ), 64>>>();
    k_scan2<<<BSZ * NH, 256>>>();
    k_scan3<<<dim3(NC, NH, BSZ), 64>>>(Dv);
    k_gate<<<TT, 256>>>(gnw);
    k_gemm_bf<<<dim3(DM/256, TT/128), 256, GSMEM>>>(
        pgh, pgl, pw2h, pw2l, out, x, TT, DM, DI);
}

// round 6
// speedup vs baseline: 2.4465x; 1.0435x over previous
#include <cuda_runtime.h>
#include <cuda_bf16.h>
#include <math.h>
#include <stdint.h>

#define BSZ 2
#define LEN 4096
#define TT (BSZ*LEN)          // 8192 tokens
#define DM 768
#define DI 1536
#define DS 16
#define NH 24
#define HD 64
#define CD 1568               // DI + 2*DS
#define DP 3128               // 2*DI + 2*DS + NH
#define NP1 3328              // DP padded to 256
#define NC 64                 // chunks
#define CH 64                 // chunk length (LEN/NC)

// ---------------- scratch (static device arrays; no runtime alloc) ----------
__device__ __align__(16) float g_zx[(size_t)TT*DP];
__device__ __align__(16) float g_xbc[(size_t)TT*CD];
__device__ float g_dt[TT*NH];
__device__ float g_dA[TT*NH];
__device__ __align__(16) float g_y[(size_t)TT*DI];
__device__ __align__(16) float g_hl[BSZ*NH*NC*HD*DS];
__device__ __align__(16) float g_hs[BSZ*NH*NC*HD*DS];
__device__ float g_P[BSZ*NH*NC];
// bf16 hi/lo operand buffers (16B aligned for cp.async)
__device__ __align__(16) __nv_bfloat16 g_uh[(size_t)TT*DM];
__device__ __align__(16) __nv_bfloat16 g_ul[(size_t)TT*DM];
__device__ __align__(16) __nv_bfloat16 g_W1h[(size_t)NP1*DM];
__device__ __align__(16) __nv_bfloat16 g_W1l[(size_t)NP1*DM];
__device__ __align__(16) __nv_bfloat16 g_gh[(size_t)TT*DI];
__device__ __align__(16) __nv_bfloat16 g_gl[(size_t)TT*DI];
__device__ __align__(16) __nv_bfloat16 g_W2h[(size_t)DM*DI];
__device__ __align__(16) __nv_bfloat16 g_W2l[(size_t)DM*DI];

__device__ __forceinline__ void split1(float v, __nv_bfloat16* ph, __nv_bfloat16* pl) {
    __nv_bfloat16 h = __float2bfloat16_rn(v);
    *ph = h;
    *pl = __float2bfloat16_rn(v - __bfloat162float(h));
}

// ---------------- weight split ----------------------------------------------
__global__ void k_split(const float* __restrict__ W, __nv_bfloat16* __restrict__ H,
                        __nv_bfloat16* __restrict__ L, int n, int nPad) {
    int i = blockIdx.x * 256 + threadIdx.x;
    if (i >= nPad) return;
    float v = (i < n) ? W[i] : 0.f;
    split1(v, H + i, L + i);
}

// ---------------- layernorm -> bf16 hi/lo ------------------------------------
__global__ void k_ln(const float* __restrict__ x, const float* __restrict__ w,
                     const float* __restrict__ bb) {
    int row = blockIdx.x;
    int tid = threadIdx.x;
    const float* xr = x + (size_t)row * DM;
    float v0 = xr[tid], v1 = xr[tid + 256], v2 = xr[tid + 512];
    float s  = v0 + v1 + v2;
    float sq = v0*v0 + v1*v1 + v2*v2;
    __shared__ float sh[16];
    #pragma unroll
    for (int m = 16; m; m >>= 1) {
        s  += __shfl_xor_sync(0xffffffffu, s,  m);
        sq += __shfl_xor_sync(0xffffffffu, sq, m);
    }
    if ((tid & 31) == 0) { sh[tid >> 5] = s; sh[8 + (tid >> 5)] = sq; }
    __syncthreads();
    if (tid < 32) {
        float a  = (tid < 8) ? sh[tid]     : 0.f;
        float b2 = (tid < 8) ? sh[8 + tid] : 0.f;
        #pragma unroll
        for (int m = 4; m; m >>= 1) {
            a  += __shfl_xor_sync(0xffffffffu, a,  m);
            b2 += __shfl_xor_sync(0xffffffffu, b2, m);
        }
        if (tid == 0) { sh[0] = a; sh[8] = b2; }
    }
    __syncthreads();
    float mu  = sh[0] * (1.f / DM);
    float var = sh[8] * (1.f / DM) - mu * mu;
    float inv = rsqrtf(var + 1e-5f);
    size_t base = (size_t)row * DM;
    float u0 = (v0 - mu) * inv * w[tid]       + bb[tid];
    float u1 = (v1 - mu) * inv * w[tid + 256] + bb[tid + 256];
    float u2 = (v2 - mu) * inv * w[tid + 512] + bb[tid + 512];
    split1(u0, g_uh + base + tid,       g_ul + base + tid);
    split1(u1, g_uh + base + tid + 256, g_ul + base + tid + 256);
    split1(u2, g_uh + base + tid + 512, g_ul + base + tid + 512);
}

// ============================================================================
// HMMA NT GEMM, pre-split bf16 hi/lo, 3-pass.
// CTA tile 128x256, 16 warps, warp tile 64x32. 3-stage cp.async, ldmatrix.x4.
// M%128==0, K%32==0, B padded to grid N.
// ============================================================================
#define SP 40                   // smem row pitch in bf16 (32 data + 8 pad)
#define A_ELE (128*SP)          // 5120
#define B_ELE (256*SP)          // 10240
#define OFF_AH 0
#define OFF_AL (A_ELE*2)
#define OFF_BH (2*A_ELE*2)
#define OFF_BL (2*A_ELE*2 + B_ELE*2)
#define STAGE_B (2*A_ELE*2 + 2*B_ELE*2)   // 61440 bytes
#define GSMEM (3*STAGE_B)

__device__ __forceinline__ uint32_t smaddr(const void* p) {
    return (uint32_t)__cvta_generic_to_shared(p);
}
#define CPA(d, s) asm volatile("cp.async.cg.shared.global [%0], [%1], 16;\n" :: "r"(d), "l"(s))
#define CPCOMMIT() asm volatile("cp.async.commit_group;\n")
#define CPWAIT1() asm volatile("cp.async.wait_group 1;\n")
#define LDSM4(r0,r1,r2,r3,a) asm volatile( \
    "ldmatrix.sync.aligned.m8n8.x4.shared.b16 {%0,%1,%2,%3}, [%4];\n" \
    : "=r"(r0),"=r"(r1),"=r"(r2),"=r"(r3) : "r"(a))
#define MMA(d, a, b0, b1) \
  asm volatile("mma.sync.aligned.m16n8k16.row.col.f32.bf16.bf16.f32 " \
      "{%0,%1,%2,%3}, {%4,%5,%6,%7}, {%8,%9}, {%0,%1,%2,%3};\n" \
      : "+f"(d[0]), "+f"(d[1]), "+f"(d[2]), "+f"(d[3]) \
      : "r"(a[0]), "r"(a[1]), "r"(a[2]), "r"(a[3]), "r"(b0), "r"(b1))

__global__ void __launch_bounds__(512, 1)
k_gemm_bf(const __nv_bfloat16* __restrict__ Ah, const __nv_bfloat16* __restrict__ Al,
          const __nv_bfloat16* __restrict__ Bh, const __nv_bfloat16* __restrict__ Bl,
          float* __restrict__ C, const float* __restrict__ R,
          int M, int N, int K) {
    extern __shared__ __nv_bfloat16 sm[];
    const int tid = threadIdx.x;
    const int warp = tid >> 5, lane = tid & 31;
    const int wm = (warp & 1) * 64;        // 2 m-positions
    const int wn = (warp >> 1) * 32;       // 8 n-positions
    const int bm = blockIdx.y * 128, bn = blockIdx.x * 256;
    const int nIter = K >> 5;

    // cp.async mapping: A uses all 512 threads once; B twice.
    const int ar = tid >> 2;               // 0..127
    const int ac = (tid & 3) << 3;         // elem offset 0,8,16,24
    const uint32_t smb = smaddr(sm);

    const int a_r = lane & 15, a_k = (lane >> 4) << 3;
    const int b_r = (lane & 7) + ((lane >> 4) << 3);
    const int b_k = ((lane >> 3) & 1) << 3;

    float acc[4][4][4];
    #pragma unroll
    for (int i = 0; i < 4; i++)
        #pragma unroll
        for (int j = 0; j < 4; j++)
            #pragma unroll
            for (int k = 0; k < 4; k++) acc[i][j][k] = 0.f;

    #define ISSUE(kt) do {                                                     \
        int _b = (kt) % 3, _k = (kt) << 5;                                     \
        uint32_t _sb = smb + (uint32_t)_b * STAGE_B;                           \
        {                                                                      \
            uint32_t _d = (uint32_t)(ar * SP + ac) * 2;                        \
            size_t _g = (size_t)(bm + ar) * K + _k + ac;                       \
            CPA(_sb + OFF_AH + _d, Ah + _g);                                   \
            CPA(_sb + OFF_AL + _d, Al + _g);                                   \
        }                                                                      \
        _Pragma("unroll")                                                      \
        for (int _i = 0; _i < 2; _i++) {                                       \
            int _r = ar + 128 * _i;                                            \
            uint32_t _d = (uint32_t)(_r * SP + ac) * 2;                        \
            size_t _g = (size_t)(bn + _r) * K + _k + ac;                       \
            CPA(_sb + OFF_BH + _d, Bh + _g);                                   \
            CPA(_sb + OFF_BL + _d, Bl + _g);                                   \
        }                                                                      \
        CPCOMMIT();                                                            \
    } while (0)

    ISSUE(0);
    ISSUE(1);

    for (int kt = 0; kt < nIter; kt++) {
        CPWAIT1();
        __syncthreads();
        const int s = kt % 3;
        const uint32_t sb = smb + (uint32_t)s * STAGE_B;

        #pragma unroll
        for (int sub = 0; sub < 32; sub += 16) {
            unsigned bh[2][4], bl[2][4];
            #pragma unroll
            for (int p = 0; p < 2; p++) {
                uint32_t ba = sb + (uint32_t)((wn + p*16 + b_r) * SP + sub + b_k) * 2;
                LDSM4(bh[p][0], bh[p][1], bh[p][2], bh[p][3], ba + OFF_BH);
                LDSM4(bl[p][0], bl[p][1], bl[p][2], bl[p][3], ba + OFF_BL);
            }
            #pragma unroll
            for (int mt = 0; mt < 4; mt++) {
                unsigned ah[4], al[4];
                uint32_t aa = sb + (uint32_t)((wm + mt*16 + a_r) * SP + sub + a_k) * 2;
                LDSM4(ah[0], ah[1], ah[2], ah[3], aa + OFF_AH);
                LDSM4(al[0], al[1], al[2], al[3], aa + OFF_AL);
                #pragma unroll
                for (int p = 0; p < 2; p++) {
                    MMA(acc[mt][2*p],   ah, bh[p][0], bh[p][1]);
                    MMA(acc[mt][2*p],   ah, bl[p][0], bl[p][1]);
                    MMA(acc[mt][2*p],   al, bh[p][0], bh[p][1]);
                    MMA(acc[mt][2*p+1], ah, bh[p][2], bh[p][3]);
                    MMA(acc[mt][2*p+1], ah, bl[p][2], bl[p][3]);
                    MMA(acc[mt][2*p+1], al, bh[p][2], bh[p][3]);
                }
            }
        }

        int nk = kt + 2;
        if (nk < nIter) { ISSUE(nk); }
        else            { CPCOMMIT(); }
    }

    // epilogue
    const int g = lane >> 2, q = lane & 3;
    #pragma unroll
    for (int mt = 0; mt < 4; mt++) {
        int row0 = bm + wm + mt * 16 + g;
        #pragma unroll
        for (int nt = 0; nt < 4; nt++) {
            int col = bn + wn + nt * 8 + 2 * q;
            if (col < N) {
                float2 v0, v1;
                v0.x = acc[mt][nt][0]; v0.y = acc[mt][nt][1];
                v1.x = acc[mt][nt][2]; v1.y = acc[mt][nt][3];
                if (R) {
                    const float* rr0 = R + (size_t)row0 * N + col;
                    const float* rr1 = R + (size_t)(row0 + 8) * N + col;
                    v0.x += rr0[0]; v0.y += rr0[1];
                    v1.x += rr1[0]; v1.y += rr1[1];
                }
                *(float2*)(C + (size_t)row0 * N + col) = v0;
                *(float2*)(C + (size_t)(row0 + 8) * N + col) = v1;
            }
        }
    }
    #undef ISSUE
}

// ---------------- dt = softplus(raw + bias), dA = exp(dt * -exp(A_log)) -----
__global__ void k_dtda(const float* __restrict__ dtb, const float* __restrict__ alog) {
    int i = blockIdx.x * 256 + threadIdx.x;
    if (i >= TT * NH) return;
    int h = i % NH, t = i / NH;
    float xv = g_zx[(size_t)t * DP + (DI + CD) + h] + dtb[h];
    float dt = (xv > 20.f) ? xv : log1pf(expf(xv));
    float A = -expf(alog[h]);
    g_dt[i] = dt;
    g_dA[i] = expf(dt * A);
}

// ---------------- causal depthwise conv(4): smem-tiled -----------------------
// block: 32 tokens x 224 channels; grid (CD/224, TT/32)
#define CT 32
#define CC 224
__global__ void __launch_bounds__(256)
k_conv(const float* __restrict__ cw, const float* __restrict__ cb) {
    __shared__ float sx[(CT + 3) * CC];
    __shared__ float swt[CC * 4];
    __shared__ float sbi[CC];
    int c0 = blockIdx.x * CC;
    int tblk = blockIdx.y;           // 0..TT/32-1
    int b = (tblk * CT) / LEN;
    int l0 = (tblk * CT) % LEN;
    int tid = threadIdx.x;

    for (int i = tid; i < CC * 4; i += 256) swt[i] = cw[c0 * 4 + i];
    for (int i = tid; i < CC; i += 256)     sbi[i] = cb[c0 + i];
    for (int i = tid; i < (CT + 3) * CC; i += 256) {
        int r = i / CC, c = i % CC;
        int l = l0 - 3 + r;
        sx[i] = (l >= 0) ? g_zx[((size_t)(b * LEN + l)) * DP + DI + c0 + c] : 0.f;
    }
    __syncthreads();

    for (int i = tid; i < CT * CC; i += 256) {
        int t = i / CC, c = i % CC;
        const float* w4 = &swt[c * 4];
        float acc = sbi[c];
        acc = fmaf(sx[(t + 0) * CC + c], w4[0], acc);
        acc = fmaf(sx[(t + 1) * CC + c], w4[1], acc);
        acc = fmaf(sx[(t + 2) * CC + c], w4[2], acc);
        acc = fmaf(sx[(t + 3) * CC + c], w4[3], acc);
        g_xbc[((size_t)(b * LEN + l0 + t)) * CD + c0 + c] = acc / (1.f + expf(-acc));
    }
}

// ---------------- scan phase 1: thread-per-p, h[16] in registers ------------
__global__ void __launch_bounds__(64)
k_scan1() {
    int c = blockIdx.x, hd = blockIdx.y, b = blockIdx.z;
    int p = threadIdx.x;
    __shared__ float sx[CH * HD];
    __shared__ __align__(16) float sB[CH * DS];
    __shared__ float sdt[CH];
    __shared__ float sdA[CH];
    int t0 = c * CH;
    size_t rb = ((size_t)(b * LEN + t0)) * CD;
    for (int idx = p; idx < CH * HD; idx += 64) {
        int t = idx >> 6, pp = idx & 63;
        sx[idx] = g_xbc[rb + (size_t)t * CD + hd * HD + pp];
    }
    for (int idx = p; idx < CH * DS; idx += 64) {
        int t = idx >> 4, n = idx & 15;
        sB[idx] = g_xbc[rb + (size_t)t * CD + DI + n];
    }
    {
        int tg = (b * LEN + t0 + p) * NH + hd;
        sdt[p] = g_dt[tg];
        sdA[p] = g_dA[tg];
    }
    __syncthreads();
    float h[16];
    #pragma unroll
    for (int n = 0; n < 16; n++) h[n] = 0.f;
    float run = 1.f;
    for (int t = 0; t < CH; t++) {
        float dA = sdA[t];
        float s = sdt[t] * sx[t * HD + p];
        run *= dA;
        #pragma unroll
        for (int n = 0; n < 16; n += 4) {
            float4 Bv = *(const float4*)&sB[t * DS + n];
            h[n]   = fmaf(dA, h[n],   s * Bv.x);
            h[n+1] = fmaf(dA, h[n+1], s * Bv.y);
            h[n+2] = fmaf(dA, h[n+2], s * Bv.z);
            h[n+3] = fmaf(dA, h[n+3], s * Bv.w);
        }
    }
    size_t base = ((size_t)((b * NH + hd) * NC + c)) * (HD * DS);
    #pragma unroll
    for (int n = 0; n < 16; n += 4)
        *(float4*)&g_hl[base + p * DS + n] = make_float4(h[n], h[n+1], h[n+2], h[n+3]);
    if (p == 0) g_P[(b * NH + hd) * NC + c] = run;
}

// ---------------- scan phase 2: inter-chunk combine (48 blocks, sequential) -
__global__ void k_scan2() {
    int bh = blockIdx.x, tid = threadIdx.x;
    float H0 = 0.f, H1 = 0.f, H2 = 0.f, H3 = 0.f;
    for (int c = 0; c < NC; c++) {
        size_t base = ((size_t)(bh * NC + c)) * (HD * DS);
        float P = g_P[bh * NC + c];
        g_hs[base + tid]       = H0;
        g_hs[base + tid + 256] = H1;
        g_hs[base + tid + 512] = H2;
        g_hs[base + tid + 768] = H3;
        H0 = P * H0 + g_hl[base + tid];
        H1 = P * H1 + g_hl[base + tid + 256];
        H2 = P * H2 + g_hl[base + tid + 512];
        H3 = P * H3 + g_hl[base + tid + 768];
    }
}

// ---------------- scan phase 3: thread-per-p, emits y ------------------------
__global__ void __launch_bounds__(64)
k_scan3(const float* __restrict__ Dp) {
    int c = blockIdx.x, hd = blockIdx.y, b = blockIdx.z;
    int p = threadIdx.x;
    __shared__ float sx[CH * HD];
    __shared__ __align__(16) float sB[CH * DS];
    __shared__ __align__(16) float sC[CH * DS];
    __shared__ float sdt[CH];
    __shared__ float sdA[CH];
    int t0 = c * CH;
    size_t rb = ((size_t)(b * LEN + t0)) * CD;
    for (int idx = p; idx < CH * HD; idx += 64) {
        int t = idx >> 6, pp = idx & 63;
        sx[idx] = g_xbc[rb + (size_t)t * CD + hd * HD + pp];
    }
    for (int idx = p; idx < CH * DS; idx += 64) {
        int t = idx >> 4, n = idx & 15;
        sB[idx] = g_xbc[rb + (size_t)t * CD + DI + n];
        sC[idx] = g_xbc[rb + (size_t)t * CD + DI + DS + n];
    }
    {
        int tg = (b * LEN + t0 + p) * NH + hd;
        sdt[p] = g_dt[tg];
        sdA[p] = g_dA[tg];
    }
    __syncthreads();
    size_t base = ((size_t)((b * NH + hd) * NC + c)) * (HD * DS);
    float h[16];
    #pragma unroll
    for (int n = 0; n < 16; n += 4) {
        float4 v = *(const float4*)&g_hs[base + p * DS + n];
        h[n] = v.x; h[n+1] = v.y; h[n+2] = v.z; h[n+3] = v.w;
    }
    float Dh = Dp[hd];
    for (int t = 0; t < CH; t++) {
        float dA = sdA[t];
        float xv = sx[t * HD + p];
        float s = sdt[t] * xv;
        float y = 0.f;
        #pragma unroll
        for (int n = 0; n < 16; n += 4) {
            float4 Bv = *(const float4*)&sB[t * DS + n];
            float4 Cv = *(const float4*)&sC[t * DS + n];
            h[n]   = fmaf(dA, h[n],   s * Bv.x);
            h[n+1] = fmaf(dA, h[n+1], s * Bv.y);
            h[n+2] = fmaf(dA, h[n+2], s * Bv.z);
            h[n+3] = fmaf(dA, h[n+3], s * Bv.w);
            y += h[n]*Cv.x + h[n+1]*Cv.y + h[n+2]*Cv.z + h[n+3]*Cv.w;
        }
        g_y[((size_t)(b * LEN + t0 + t)) * DI + hd * HD + p] = y + Dh * xv;
    }
}

// ---------------- gating + RMSNorm -> bf16 hi/lo ----------------------------
__global__ void k_gate(const float* __restrict__ gnw) {
    int row = blockIdx.x, tid = threadIdx.x;
    const float* yr = g_y  + (size_t)row * DI;
    const float* zr = g_zx + (size_t)row * DP;
    float gv[6];
    float sq = 0.f;
    #pragma unroll
    for (int i = 0; i < 6; i++) {
        int cc = tid + 256 * i;
        float z = zr[cc];
        float g = yr[cc] * (z / (1.f + expf(-z)));
        gv[i] = g;
        sq += g * g;
    }
    __shared__ float sh[8];
    #pragma unroll
    for (int m = 16; m; m >>= 1) sq += __shfl_xor_sync(0xffffffffu, sq, m);
    if ((tid & 31) == 0) sh[tid >> 5] = sq;
    __syncthreads();
    if (tid < 32) {
        float a = (tid < 8) ? sh[tid] : 0.f;
        #pragma unroll
        for (int m = 4; m; m >>= 1) a += __shfl_xor_sync(0xffffffffu, a, m);
        if (tid == 0) sh[0] = a;
    }
    __syncthreads();
    float inv = rsqrtf(sh[0] * (1.f / DI) + 1e-5f);
    size_t base = (size_t)row * DI;
    #pragma unroll
    for (int i = 0; i < 6; i++) {
        int cc = tid + 256 * i;
        split1(gv[i] * inv * gnw[cc], g_gh + base + cc, g_gl + base + cc);
    }
}

// ---------------- launcher ---------------------------------------------------
extern "C" void kernel_launch(void* const* d_in, const int* in_sizes, int n_in,
                              void* d_out, int out_size) {
    const float* x       = (const float*)d_in[0];
    const float* ln_w    = (const float*)d_in[1];
    const float* ln_b    = (const float*)d_in[2];
    const float* W_in    = (const float*)d_in[3];
    const float* conv_w  = (const float*)d_in[4];
    const float* conv_b  = (const float*)d_in[5];
    const float* dt_bias = (const float*)d_in[6];
    const float* A_log   = (const float*)d_in[7];
    const float* Dv      = (const float*)d_in[8];
    const float* gnw     = (const float*)d_in[9];
    const float* W_out   = (const float*)d_in[10];
    float* out = (float*)d_out;

    __nv_bfloat16 *puh, *pul, *pw1h, *pw1l, *pgh, *pgl, *pw2h, *pw2l;
    float *pzx;
    cudaGetSymbolAddress((void**)&pzx,  g_zx);
    cudaGetSymbolAddress((void**)&puh,  g_uh);
    cudaGetSymbolAddress((void**)&pul,  g_ul);
    cudaGetSymbolAddress((void**)&pw1h, g_W1h);
    cudaGetSymbolAddress((void**)&pw1l, g_W1l);
    cudaGetSymbolAddress((void**)&pgh,  g_gh);
    cudaGetSymbolAddress((void**)&pgl,  g_gl);
    cudaGetSymbolAddress((void**)&pw2h, g_W2h);
    cudaGetSymbolAddress((void**)&pw2l, g_W2l);

    cudaFuncSetAttribute(k_gemm_bf, cudaFuncAttributeMaxDynamicSharedMemorySize, GSMEM);

    k_split<<<(NP1*DM + 255)/256, 256>>>(W_in,  pw1h, pw1l, DP*DM, NP1*DM);
    k_split<<<(DM*DI + 255)/256, 256>>>(W_out, pw2h, pw2l, DM*DI, DM*DI);
    k_ln<<<TT, 256>>>(x, ln_w, ln_b);
    k_gemm_bf<<<dim3(NP1/256, TT/128), 512, GSMEM>>>(
        puh, pul, pw1h, pw1l, pzx, nullptr, TT, DP, DM);
    k_dtda<<<(TT * NH + 255) / 256, 256>>>(dt_bias, A_log);
    k_conv<<<dim3(CD/CC, TT/CT), 256>>>(conv_w, conv_b);
    k_scan1<<<dim3(NC, NH, BSZ), 64>>>();
    k_scan2<<<BSZ * NH, 256>>>();
    k_scan3<<<dim3(NC, NH, BSZ), 64>>>(Dv);
    k_gate<<<TT, 256>>>(gnw);
    k_gemm_bf<<<dim3(DM/256, TT/128), 512, GSMEM>>>(
        pgh, pgl, pw2h, pw2l, out, x, TT, DM, DI);
}

// round 7
// speedup vs baseline: 4.1244x; 1.6858x over previous
#include <cuda_runtime.h>
#include <cuda_fp16.h>
#include <math.h>
#include <stdint.h>

#define BSZ 2
#define LEN 4096
#define TT (BSZ*LEN)          // 8192 tokens
#define DM 768
#define DI 1536
#define DS 16
#define NH 24
#define HD 64
#define CD 1568               // DI + 2*DS
#define DP 3128               // 2*DI + 2*DS + NH
#define NP1 3200              // DP padded to 128
#define NC 64                 // chunks
#define CH 64                 // chunk length (LEN/NC)

// ---------------- scratch (static device arrays; no runtime alloc) ----------
__device__ __align__(16) float g_zx[(size_t)TT*DP];
__device__ __align__(16) float g_xbc[(size_t)TT*CD];
__device__ float g_dt[TT*NH];
__device__ float g_dA[TT*NH];
__device__ __align__(16) float g_y[(size_t)TT*DI];
__device__ __align__(16) float g_hl[BSZ*NH*NC*HD*DS];
__device__ __align__(16) float g_hs[BSZ*NH*NC*HD*DS];
__device__ float g_P[BSZ*NH*NC];
// fp16 operand buffers (16B aligned for cp.async)
__device__ __align__(16) __half g_u16[(size_t)TT*DM];
__device__ __align__(16) __half g_W1[(size_t)NP1*DM];
__device__ __align__(16) __half g_g16[(size_t)TT*DI];
__device__ __align__(16) __half g_W2[(size_t)DM*DI];

// ---------------- weight convert ---------------------------------------------
__global__ void k_cvt(const float* __restrict__ W, __half* __restrict__ H,
                      int n, int nPad) {
    int i = blockIdx.x * 256 + threadIdx.x;
    if (i >= nPad) return;
    H[i] = __float2half_rn((i < n) ? W[i] : 0.f);
}

// ---------------- layernorm -> fp16 ------------------------------------------
__global__ void k_ln(const float* __restrict__ x, const float* __restrict__ w,
                     const float* __restrict__ bb) {
    int row = blockIdx.x;
    int tid = threadIdx.x;
    const float* xr = x + (size_t)row * DM;
    float v0 = xr[tid], v1 = xr[tid + 256], v2 = xr[tid + 512];
    float s  = v0 + v1 + v2;
    float sq = v0*v0 + v1*v1 + v2*v2;
    __shared__ float sh[16];
    #pragma unroll
    for (int m = 16; m; m >>= 1) {
        s  += __shfl_xor_sync(0xffffffffu, s,  m);
        sq += __shfl_xor_sync(0xffffffffu, sq, m);
    }
    if ((tid & 31) == 0) { sh[tid >> 5] = s; sh[8 + (tid >> 5)] = sq; }
    __syncthreads();
    if (tid < 32) {
        float a  = (tid < 8) ? sh[tid]     : 0.f;
        float b2 = (tid < 8) ? sh[8 + tid] : 0.f;
        #pragma unroll
        for (int m = 4; m; m >>= 1) {
            a  += __shfl_xor_sync(0xffffffffu, a,  m);
            b2 += __shfl_xor_sync(0xffffffffu, b2, m);
        }
        if (tid == 0) { sh[0] = a; sh[8] = b2; }
    }
    __syncthreads();
    float mu  = sh[0] * (1.f / DM);
    float var = sh[8] * (1.f / DM) - mu * mu;
    float inv = rsqrtf(var + 1e-5f);
    size_t base = (size_t)row * DM;
    g_u16[base + tid]       = __float2half_rn((v0 - mu) * inv * w[tid]       + bb[tid]);
    g_u16[base + tid + 256] = __float2half_rn((v1 - mu) * inv * w[tid + 256] + bb[tid + 256]);
    g_u16[base + tid + 512] = __float2half_rn((v2 - mu) * inv * w[tid + 512] + bb[tid + 512]);
}

// ============================================================================
// fp16 single-pass HMMA NT GEMM: C[M,N] = A[M,K]*B[N,K]^T (+R).
// CTA tile 128x128x32, 8 warps (warp tile 64x32), 3-stage cp.async, ldmatrix.x4.
// 2 CTAs/SM. M%128==0, K%32==0, B padded so grid-N loads valid; stores col<N.
// ============================================================================
#define SP 40                     // smem row pitch in halves (32 data + 8 pad)
#define A_ELE (128*SP)
#define OFF_A 0
#define OFF_B (A_ELE*2)
#define STAGE_B (2*A_ELE*2)       // 20480 bytes
#define GSMEM (3*STAGE_B)         // 61440 bytes

__device__ __forceinline__ uint32_t smaddr(const void* p) {
    return (uint32_t)__cvta_generic_to_shared(p);
}
#define CPA(d, s) asm volatile("cp.async.cg.shared.global [%0], [%1], 16;\n" :: "r"(d), "l"(s))
#define CPCOMMIT() asm volatile("cp.async.commit_group;\n")
#define CPWAIT1() asm volatile("cp.async.wait_group 1;\n")
#define LDSM4(r0,r1,r2,r3,a) asm volatile( \
    "ldmatrix.sync.aligned.m8n8.x4.shared.b16 {%0,%1,%2,%3}, [%4];\n" \
    : "=r"(r0),"=r"(r1),"=r"(r2),"=r"(r3) : "r"(a))
#define MMAH(d, a, b0, b1) \
  asm volatile("mma.sync.aligned.m16n8k16.row.col.f32.f16.f16.f32 " \
      "{%0,%1,%2,%3}, {%4,%5,%6,%7}, {%8,%9}, {%0,%1,%2,%3};\n" \
      : "+f"(d[0]), "+f"(d[1]), "+f"(d[2]), "+f"(d[3]) \
      : "r"(a[0]), "r"(a[1]), "r"(a[2]), "r"(a[3]), "r"(b0), "r"(b1))

__global__ void __launch_bounds__(256, 2)
k_gemm_h(const __half* __restrict__ A, const __half* __restrict__ B,
         float* __restrict__ C, const float* __restrict__ R,
         int M, int N, int K) {
    extern __shared__ __half sm[];
    const int tid = threadIdx.x;
    const int warp = tid >> 5, lane = tid & 31;
    const int wm = (warp & 1) * 64;        // 2 m-positions
    const int wn = (warp >> 1) * 32;       // 4 n-positions
    const int bm = blockIdx.y * 128, bn = blockIdx.x * 128;
    const int nIter = K >> 5;
    const uint32_t smb = smaddr(sm);

    const int a_r = lane & 15, a_k = (lane >> 4) << 3;
    const int b_r = (lane & 7) + ((lane >> 4) << 3);
    const int b_k = ((lane >> 3) & 1) << 3;

    float acc[4][4][4];
    #pragma unroll
    for (int i = 0; i < 4; i++)
        #pragma unroll
        for (int j = 0; j < 4; j++)
            #pragma unroll
            for (int k = 0; k < 4; k++) acc[i][j][k] = 0.f;

    #define ISSUE(kt) do {                                                     \
        int _b = (kt) % 3, _k = (kt) << 5;                                     \
        uint32_t _sb = smb + (uint32_t)_b * STAGE_B;                           \
        _Pragma("unroll")                                                      \
        for (int _i = 0; _i < 2; _i++) {                                       \
            int _idx = tid + 256 * _i;                                         \
            int _r = _idx >> 2, _c = (_idx & 3) << 3;                          \
            uint32_t _d = (uint32_t)(_r * SP + _c) * 2;                        \
            CPA(_sb + OFF_A + _d, A + (size_t)(bm + _r) * K + _k + _c);        \
            CPA(_sb + OFF_B + _d, B + (size_t)(bn + _r) * K + _k + _c);        \
        }                                                                      \
        CPCOMMIT();                                                            \
    } while (0)

    ISSUE(0);
    ISSUE(1);

    for (int kt = 0; kt < nIter; kt++) {
        CPWAIT1();
        __syncthreads();
        const int s = kt % 3;
        const uint32_t sb = smb + (uint32_t)s * STAGE_B;

        #pragma unroll
        for (int sub = 0; sub < 32; sub += 16) {
            unsigned bh[2][4];
            #pragma unroll
            for (int p = 0; p < 2; p++) {
                uint32_t ba = sb + OFF_B +
                    (uint32_t)((wn + p*16 + b_r) * SP + sub + b_k) * 2;
                LDSM4(bh[p][0], bh[p][1], bh[p][2], bh[p][3], ba);
            }
            #pragma unroll
            for (int mt = 0; mt < 4; mt++) {
                unsigned ah[4];
                uint32_t aa = sb + OFF_A +
                    (uint32_t)((wm + mt*16 + a_r) * SP + sub + a_k) * 2;
                LDSM4(ah[0], ah[1], ah[2], ah[3], aa);
                #pragma unroll
                for (int p = 0; p < 2; p++) {
                    MMAH(acc[mt][2*p],   ah, bh[p][0], bh[p][1]);
                    MMAH(acc[mt][2*p+1], ah, bh[p][2], bh[p][3]);
                }
            }
        }

        int nk = kt + 2;
        if (nk < nIter) { ISSUE(nk); }
        else            { CPCOMMIT(); }
    }

    // epilogue
    const int g = lane >> 2, q = lane & 3;
    #pragma unroll
    for (int mt = 0; mt < 4; mt++) {
        int row0 = bm + wm + mt * 16 + g;
        #pragma unroll
        for (int nt = 0; nt < 4; nt++) {
            int col = bn + wn + nt * 8 + 2 * q;
            if (col < N) {
                float2 v0, v1;
                v0.x = acc[mt][nt][0]; v0.y = acc[mt][nt][1];
                v1.x = acc[mt][nt][2]; v1.y = acc[mt][nt][3];
                if (R) {
                    const float* rr0 = R + (size_t)row0 * N + col;
                    const float* rr1 = R + (size_t)(row0 + 8) * N + col;
                    v0.x += rr0[0]; v0.y += rr0[1];
                    v1.x += rr1[0]; v1.y += rr1[1];
                }
                *(float2*)(C + (size_t)row0 * N + col) = v0;
                *(float2*)(C + (size_t)(row0 + 8) * N + col) = v1;
            }
        }
    }
    #undef ISSUE
}

// ---------------- dt = softplus(raw + bias), dA = exp(dt * -exp(A_log)) -----
__global__ void k_dtda(const float* __restrict__ dtb, const float* __restrict__ alog) {
    int i = blockIdx.x * 256 + threadIdx.x;
    if (i >= TT * NH) return;
    int h = i % NH, t = i / NH;
    float xv = g_zx[(size_t)t * DP + (DI + CD) + h] + dtb[h];
    float dt = (xv > 20.f) ? xv : log1pf(expf(xv));
    float A = -expf(alog[h]);
    g_dt[i] = dt;
    g_dA[i] = expf(dt * A);
}

// ---------------- causal depthwise conv(4): smem-tiled -----------------------
#define CT 32
#define CC 224
__global__ void __launch_bounds__(256)
k_conv(const float* __restrict__ cw, const float* __restrict__ cb) {
    __shared__ float sx[(CT + 3) * CC];
    __shared__ float swt[CC * 4];
    __shared__ float sbi[CC];
    int c0 = blockIdx.x * CC;
    int tblk = blockIdx.y;
    int b = (tblk * CT) / LEN;
    int l0 = (tblk * CT) % LEN;
    int tid = threadIdx.x;

    for (int i = tid; i < CC * 4; i += 256) swt[i] = cw[c0 * 4 + i];
    for (int i = tid; i < CC; i += 256)     sbi[i] = cb[c0 + i];
    for (int i = tid; i < (CT + 3) * CC; i += 256) {
        int r = i / CC, c = i % CC;
        int l = l0 - 3 + r;
        sx[i] = (l >= 0) ? g_zx[((size_t)(b * LEN + l)) * DP + DI + c0 + c] : 0.f;
    }
    __syncthreads();

    for (int i = tid; i < CT * CC; i += 256) {
        int t = i / CC, c = i % CC;
        const float* w4 = &swt[c * 4];
        float acc = sbi[c];
        acc = fmaf(sx[(t + 0) * CC + c], w4[0], acc);
        acc = fmaf(sx[(t + 1) * CC + c], w4[1], acc);
        acc = fmaf(sx[(t + 2) * CC + c], w4[2], acc);
        acc = fmaf(sx[(t + 3) * CC + c], w4[3], acc);
        g_xbc[((size_t)(b * LEN + l0 + t)) * CD + c0 + c] = acc / (1.f + expf(-acc));
    }
}

// ---------------- scan phase 1: thread-per-p, h[16] in registers ------------
__global__ void __launch_bounds__(64)
k_scan1() {
    int c = blockIdx.x, hd = blockIdx.y, b = blockIdx.z;
    int p = threadIdx.x;
    __shared__ float sx[CH * HD];
    __shared__ __align__(16) float sB[CH * DS];
    __shared__ float sdt[CH];
    __shared__ float sdA[CH];
    int t0 = c * CH;
    size_t rb = ((size_t)(b * LEN + t0)) * CD;
    for (int idx = p; idx < CH * HD; idx += 64) {
        int t = idx >> 6, pp = idx & 63;
        sx[idx] = g_xbc[rb + (size_t)t * CD + hd * HD + pp];
    }
    for (int idx = p; idx < CH * DS; idx += 64) {
        int t = idx >> 4, n = idx & 15;
        sB[idx] = g_xbc[rb + (size_t)t * CD + DI + n];
    }
    {
        int tg = (b * LEN + t0 + p) * NH + hd;
        sdt[p] = g_dt[tg];
        sdA[p] = g_dA[tg];
    }
    __syncthreads();
    float h[16];
    #pragma unroll
    for (int n = 0; n < 16; n++) h[n] = 0.f;
    float run = 1.f;
    for (int t = 0; t < CH; t++) {
        float dA = sdA[t];
        float s = sdt[t] * sx[t * HD + p];
        run *= dA;
        #pragma unroll
        for (int n = 0; n < 16; n += 4) {
            float4 Bv = *(const float4*)&sB[t * DS + n];
            h[n]   = fmaf(dA, h[n],   s * Bv.x);
            h[n+1] = fmaf(dA, h[n+1], s * Bv.y);
            h[n+2] = fmaf(dA, h[n+2], s * Bv.z);
            h[n+3] = fmaf(dA, h[n+3], s * Bv.w);
        }
    }
    size_t base = ((size_t)((b * NH + hd) * NC + c)) * (HD * DS);
    #pragma unroll
    for (int n = 0; n < 16; n += 4)
        *(float4*)&g_hl[base + p * DS + n] = make_float4(h[n], h[n+1], h[n+2], h[n+3]);
    if (p == 0) g_P[(b * NH + hd) * NC + c] = run;
}

// ---------------- scan phase 2: inter-chunk combine --------------------------
__global__ void k_scan2() {
    int bh = blockIdx.x, tid = threadIdx.x;
    float H0 = 0.f, H1 = 0.f, H2 = 0.f, H3 = 0.f;
    for (int c = 0; c < NC; c++) {
        size_t base = ((size_t)(bh * NC + c)) * (HD * DS);
        float P = g_P[bh * NC + c];
        g_hs[base + tid]       = H0;
        g_hs[base + tid + 256] = H1;
        g_hs[base + tid + 512] = H2;
        g_hs[base + tid + 768] = H3;
        H0 = P * H0 + g_hl[base + tid];
        H1 = P * H1 + g_hl[base + tid + 256];
        H2 = P * H2 + g_hl[base + tid + 512];
        H3 = P * H3 + g_hl[base + tid + 768];
    }
}

// ---------------- scan phase 3: thread-per-p, emits y ------------------------
__global__ void __launch_bounds__(64)
k_scan3(const float* __restrict__ Dp) {
    int c = blockIdx.x, hd = blockIdx.y, b = blockIdx.z;
    int p = threadIdx.x;
    __shared__ float sx[CH * HD];
    __shared__ __align__(16) float sB[CH * DS];
    __shared__ __align__(16) float sC[CH * DS];
    __shared__ float sdt[CH];
    __shared__ float sdA[CH];
    int t0 = c * CH;
    size_t rb = ((size_t)(b * LEN + t0)) * CD;
    for (int idx = p; idx < CH * HD; idx += 64) {
        int t = idx >> 6, pp = idx & 63;
        sx[idx] = g_xbc[rb + (size_t)t * CD + hd * HD + pp];
    }
    for (int idx = p; idx < CH * DS; idx += 64) {
        int t = idx >> 4, n = idx & 15;
        sB[idx] = g_xbc[rb + (size_t)t * CD + DI + n];
        sC[idx] = g_xbc[rb + (size_t)t * CD + DI + DS + n];
    }
    {
        int tg = (b * LEN + t0 + p) * NH + hd;
        sdt[p] = g_dt[tg];
        sdA[p] = g_dA[tg];
    }
    __syncthreads();
    size_t base = ((size_t)((b * NH + hd) * NC + c)) * (HD * DS);
    float h[16];
    #pragma unroll
    for (int n = 0; n < 16; n += 4) {
        float4 v = *(const float4*)&g_hs[base + p * DS + n];
        h[n] = v.x; h[n+1] = v.y; h[n+2] = v.z; h[n+3] = v.w;
    }
    float Dh = Dp[hd];
    for (int t = 0; t < CH; t++) {
        float dA = sdA[t];
        float xv = sx[t * HD + p];
        float s = sdt[t] * xv;
        float y = 0.f;
        #pragma unroll
        for (int n = 0; n < 16; n += 4) {
            float4 Bv = *(const float4*)&sB[t * DS + n];
            float4 Cv = *(const float4*)&sC[t * DS + n];
            h[n]   = fmaf(dA, h[n],   s * Bv.x);
            h[n+1] = fmaf(dA, h[n+1], s * Bv.y);
            h[n+2] = fmaf(dA, h[n+2], s * Bv.z);
            h[n+3] = fmaf(dA, h[n+3], s * Bv.w);
            y += h[n]*Cv.x + h[n+1]*Cv.y + h[n+2]*Cv.z + h[n+3]*Cv.w;
        }
        g_y[((size_t)(b * LEN + t0 + t)) * DI + hd * HD + p] = y + Dh * xv;
    }
}

// ---------------- gating + RMSNorm -> fp16 -----------------------------------
__global__ void k_gate(const float* __restrict__ gnw) {
    int row = blockIdx.x, tid = threadIdx.x;
    const float* yr = g_y  + (size_t)row * DI;
    const float* zr = g_zx + (size_t)row * DP;
    float gv[6];
    float sq = 0.f;
    #pragma unroll
    for (int i = 0; i < 6; i++) {
        int cc = tid + 256 * i;
        float z = zr[cc];
        float g = yr[cc] * (z / (1.f + expf(-z)));
        gv[i] = g;
        sq += g * g;
    }
    __shared__ float sh[8];
    #pragma unroll
    for (int m = 16; m; m >>= 1) sq += __shfl_xor_sync(0xffffffffu, sq, m);
    if ((tid & 31) == 0) sh[tid >> 5] = sq;
    __syncthreads();
    if (tid < 32) {
        float a = (tid < 8) ? sh[tid] : 0.f;
        #pragma unroll
        for (int m = 4; m; m >>= 1) a += __shfl_xor_sync(0xffffffffu, a, m);
        if (tid == 0) sh[0] = a;
    }
    __syncthreads();
    float inv = rsqrtf(sh[0] * (1.f / DI) + 1e-5f);
    size_t base = (size_t)row * DI;
    #pragma unroll
    for (int i = 0; i < 6; i++) {
        int cc = tid + 256 * i;
        g_g16[base + cc] = __float2half_rn(gv[i] * inv * gnw[cc]);
    }
}

// ---------------- launcher ---------------------------------------------------
extern "C" void kernel_launch(void* const* d_in, const int* in_sizes, int n_in,
                              void* d_out, int out_size) {
    const float* x       = (const float*)d_in[0];
    const float* ln_w    = (const float*)d_in[1];
    const float* ln_b    = (const float*)d_in[2];
    const float* W_in    = (const float*)d_in[3];
    const float* conv_w  = (const float*)d_in[4];
    const float* conv_b  = (const float*)d_in[5];
    const float* dt_bias = (const float*)d_in[6];
    const float* A_log   = (const float*)d_in[7];
    const float* Dv      = (const float*)d_in[8];
    const float* gnw     = (const float*)d_in[9];
    const float* W_out   = (const float*)d_in[10];
    float* out = (float*)d_out;

    __half *pu, *pw1, *pg, *pw2;
    float *pzx;
    cudaGetSymbolAddress((void**)&pzx, g_zx);
    cudaGetSymbolAddress((void**)&pu,  g_u16);
    cudaGetSymbolAddress((void**)&pw1, g_W1);
    cudaGetSymbolAddress((void**)&pg,  g_g16);
    cudaGetSymbolAddress((void**)&pw2, g_W2);

    cudaFuncSetAttribute(k_gemm_h, cudaFuncAttributeMaxDynamicSharedMemorySize, GSMEM);

    k_cvt<<<(NP1*DM + 255)/256, 256>>>(W_in,  pw1, DP*DM, NP1*DM);
    k_cvt<<<(DM*DI + 255)/256, 256>>>(W_out, pw2, DM*DI, DM*DI);
    k_ln<<<TT, 256>>>(x, ln_w, ln_b);
    k_gemm_h<<<dim3(NP1/128, TT/128), 256, GSMEM>>>(
        pu, pw1, pzx, nullptr, TT, DP, DM);
    k_dtda<<<(TT * NH + 255) / 256, 256>>>(dt_bias, A_log);
    k_conv<<<dim3(CD/CC, TT/CT), 256>>>(conv_w, conv_b);
    k_scan1<<<dim3(NC, NH, BSZ), 64>>>();
    k_scan2<<<BSZ * NH, 256>>>();
    k_scan3<<<dim3(NC, NH, BSZ), 64>>>(Dv);
    k_gate<<<TT, 256>>>(gnw);
    k_gemm_h<<<dim3(DM/128, TT/128), 256, GSMEM>>>(
        pg, pw2, out, x, TT, DM, DI);
}